// round 14
// baseline (speedup 1.0000x reference)
#include <cuda_runtime.h>
#include <cuda_fp16.h>
#include <math.h>
#include <stdint.h>

// Problem constants
#define B_    4
#define L_    2048
#define D_    768
#define H_    12
#define DH_   64
#define F_    3072
#define KS_   307              // round(0.15 * 2048)
#define BL_   (B_*L_)          // 8192
#define MSEL_ (B_*KS_)         // 1228
#define NKVM_ 2304             // 3*D concat (K,V,M)
#define NSPL_ 4                // KV splits in flash attention
#define JSEG_ (L_/NSPL_)       // 512
#define QZ_   4                // split-K for Q/Wo GEMMs

#define WSZ_  589824           // 768*768
#define W1SZ_ 2359296          // 768*3072

// ---------------- scratch (static device globals; allocation-free) ----------
__device__ __align__(16) __half g_nh[BL_*(size_t)D_];   // fp16 LN1 output
__device__ float g_scores[BL_];
__device__ float g_ssum[B_];
__device__ int   g_selidx[MSEL_];
__device__ int   g_selpos[BL_];
__device__ float g_ppart[B_*16*D_];
__device__ float g_pooled[B_*D_];
__device__ float g_pooledWm[B_*D_];
__device__ __align__(16) __half g_khf[BL_*(size_t)D_];  // fp16 K
__device__ __align__(16) __half g_vhf[BL_*(size_t)D_];  // fp16 V
__device__ float g_mixb[BL_*(size_t)D_];                // fp32 mix base
__device__ float g_bkvm[NKVM_];
__device__ __align__(16) __half g_qselh[MSEL_*(size_t)D_];
__device__ float g_po[(size_t)B_*H_*NSPL_*320*64];   // attention partial O
__device__ float g_pm[B_*H_*NSPL_*320];
__device__ float g_pl[B_*H_*NSPL_*320];
__device__ __align__(16) __half g_ctxh[MSEL_*(size_t)D_];
__device__ float g_h[BL_*(size_t)D_];
__device__ __align__(16) __half g_n2h[BL_*(size_t)D_];
__device__ __align__(16) __half g_th[BL_*(size_t)F_];
__device__ float g_fp2[2*(size_t)BL_*D_];     // split-K partials (reused: Q, Wo, FFN2)
__device__ __align__(16) __half g_whuf[5*(size_t)WSZ_ + 2*(size_t)W1SZ_];  // fp16 [N][K] weights

// ---------------- small helpers ----------------
__device__ __forceinline__ uint32_t smem_u32(const void* p) {
    uint32_t a;
    asm("{ .reg .u64 t; cvta.to.shared.u64 t, %1; cvt.u32.u64 %0, t; }"
        : "=r"(a) : "l"(p));
    return a;
}
__device__ __forceinline__ void mma16n8k16h(float* c, const uint32_t* a, const uint32_t* b) {
    asm volatile(
        "mma.sync.aligned.m16n8k16.row.col.f32.f16.f16.f32 "
        "{%0,%1,%2,%3}, {%4,%5,%6,%7}, {%8,%9}, {%0,%1,%2,%3};"
        : "+f"(c[0]), "+f"(c[1]), "+f"(c[2]), "+f"(c[3])
        : "r"(a[0]), "r"(a[1]), "r"(a[2]), "r"(a[3]), "r"(b[0]), "r"(b[1]));
}
__device__ __forceinline__ void ldsm4(uint32_t* r, uint32_t addr) {
    asm volatile("ldmatrix.sync.aligned.m8n8.x4.shared.b16 {%0,%1,%2,%3}, [%4];"
        : "=r"(r[0]), "=r"(r[1]), "=r"(r[2]), "=r"(r[3]) : "r"(addr));
}
__device__ __forceinline__ void cpasync16(uint32_t dst, const void* src, unsigned sz) {
    asm volatile("cp.async.cg.shared.global [%0], [%1], 16, %2;"
        :: "r"(dst), "l"(src), "r"(sz));
}
__device__ __forceinline__ void cpcommit() { asm volatile("cp.async.commit_group;"); }
__device__ __forceinline__ void cpwait0()  { asm volatile("cp.async.wait_group 0;"); }
__device__ __forceinline__ void cpwait1()  { asm volatile("cp.async.wait_group 1;"); }

// ---------------- reductions ----------------
__device__ __forceinline__ float blockReduceSum(float v, float* sh) {
    __syncthreads();
    int lane = threadIdx.x & 31, w = threadIdx.x >> 5;
    #pragma unroll
    for (int o = 16; o > 0; o >>= 1) v += __shfl_xor_sync(0xffffffffu, v, o);
    if (lane == 0) sh[w] = v;
    __syncthreads();
    int nw = (blockDim.x + 31) >> 5;
    if (w == 0) {
        v = (lane < nw) ? sh[lane] : 0.f;
        #pragma unroll
        for (int o = 16; o > 0; o >>= 1) v += __shfl_xor_sync(0xffffffffu, v, o);
        if (lane == 0) sh[0] = v;
    }
    __syncthreads();
    return sh[0];
}

// ---------------- W prep: fused 7-way transpose [K][N] fp32 -> [N][K] fp16 --
struct TP7 {
    const float* in[7];
    __half* out[7];
    int K[7], N[7];
    int cum[8];
};
__global__ void transpose_all_kernel(TP7 p) {
    __shared__ float tile[64][33];
    int flat = blockIdx.x;
    int s = 0;
    #pragma unroll
    for (int i = 1; i < 7; i++) s += (flat >= p.cum[i]);
    int id = flat - p.cum[s];
    int K = p.K[s], N = p.N[s];
    int ntl = N >> 5;
    int k0 = (id / ntl) * 64, n0 = (id % ntl) * 32;
    const float* in = p.in[s];
    __half* out = p.out[s];
    int tx = threadIdx.x, ty = threadIdx.y;   // (32, 8)
    #pragma unroll
    for (int i = 0; i < 64; i += 8)
        tile[ty + i][tx] = in[(size_t)(k0 + ty + i) * N + n0 + tx];
    __syncthreads();
    #pragma unroll
    for (int i = 0; i < 32; i += 8) {
        int n = n0 + ty + i;
        __half2 v = __floats2half2_rn(tile[tx*2][ty + i], tile[tx*2 + 1][ty + i]);
        *reinterpret_cast<__half2*>(&out[(size_t)n * K + k0 + tx*2]) = v;
    }
}

__global__ void bias_concat_kernel(const float* __restrict__ bk, const float* __restrict__ bv,
                                   const float* __restrict__ bm) {
    int d = blockIdx.x * 256 + threadIdx.x;
    float v = (d < 768) ? bk[d] : ((d < 1536) ? bv[d - 768] : bm[d - 1536]);
    g_bkvm[d] = v;
}

// ---------------- K1: LN1 + router score ----------------
__global__ void ln1_router_kernel(const float* __restrict__ x, const float* __restrict__ g1,
                                  const float* __restrict__ b1, const float* __restrict__ Wr,
                                  const float* __restrict__ br) {
    int tok = blockIdx.x;
    int t = threadIdx.x;   // 256
    const float* xr = x + (size_t)tok * D_;
    __shared__ float sh[32];
    float v[3]; float s = 0.f, sq = 0.f;
    #pragma unroll
    for (int i = 0; i < 3; i++) { float u = xr[t + 256*i]; v[i] = u; s += u; sq += u*u; }
    s  = blockReduceSum(s,  sh);
    sq = blockReduceSum(sq, sh);
    float mean = s * (1.f/D_);
    float var  = sq * (1.f/D_) - mean*mean;
    float rstd = rsqrtf(var + 1e-5f);
    float dot = 0.f;
    #pragma unroll
    for (int i = 0; i < 3; i++) {
        int d = t + 256*i;
        float nv = (v[i] - mean) * rstd * g1[d] + b1[d];
        g_nh[(size_t)tok*D_ + d] = __float2half_rn(nv);
        dot += nv * Wr[d];
    }
    dot = blockReduceSum(dot, sh);
    if (t == 0) g_scores[tok] = 1.f / (1.f + expf(-(dot + br[0])));
}

// ---------------- K2: exact top-k via histogram select + rank counting -----
__global__ void topk_kernel() {
    int b = blockIdx.x, t = threadIdx.x;   // 1024 threads
    __shared__ int hist[2048];
    __shared__ unsigned long long cand[2048];
    __shared__ float sh[32];
    __shared__ int wsum[32];
    __shared__ int s_thr, s_below, s_ncand, s_ndir;
    hist[t] = 0; hist[t + 1024] = 0;
    if (t == 0) { s_ncand = 0; s_ndir = 0; }
    float s0 = g_scores[b*L_ + t];
    float s1 = g_scores[b*L_ + t + 1024];
    g_selpos[b*L_ + t] = -1;
    g_selpos[b*L_ + t + 1024] = -1;
    float tot = blockReduceSum(s0 + s1, sh);
    if (t == 0) g_ssum[b] = tot + 1e-6f;
    __syncthreads();
    unsigned u0 = __float_as_uint(s0) >> 21;
    unsigned u1 = __float_as_uint(s1) >> 21;
    atomicAdd(&hist[u0], 1);
    atomicAdd(&hist[u1], 1);
    __syncthreads();
    int h0 = hist[2*t], h1 = hist[2*t + 1];
    int pair = h0 + h1;
    int lane = t & 31, wrp = t >> 5;
    int v = pair;
    #pragma unroll
    for (int o = 1; o < 32; o <<= 1) {
        int u = __shfl_up_sync(0xffffffffu, v, o);
        if (lane >= o) v += u;
    }
    if (lane == 31) wsum[wrp] = v;
    __syncthreads();
    if (wrp == 0) {
        int u = wsum[lane];
        #pragma unroll
        for (int o = 1; o < 32; o <<= 1) {
            int z = __shfl_up_sync(0xffffffffu, u, o);
            if (lane >= o) u += z;
        }
        wsum[lane] = u;
    }
    __syncthreads();
    int incl_pair = v + (wrp ? wsum[wrp - 1] : 0);
    int excl = incl_pair - pair;
    int incl0 = excl + h0;
    if (incl0 >= KS_ && excl < KS_)       { s_thr = 2*t;     s_below = excl; }
    if (incl_pair >= KS_ && incl0 < KS_)  { s_thr = 2*t + 1; s_below = incl0; }
    __syncthreads();
    const int thr = s_thr, below = s_below;
    #pragma unroll
    for (int q = 0; q < 2; q++) {
        int tok = t + q*1024;
        float sv = q ? s1 : s0;
        unsigned uv = q ? u1 : u0;
        if ((int)uv < thr) {
            int slot = atomicAdd(&s_ndir, 1);
            g_selidx[b*KS_ + slot] = b*L_ + tok;
            g_selpos[b*L_ + tok] = b*KS_ + slot;
        } else if ((int)uv == thr) {
            int c = atomicAdd(&s_ncand, 1);
            cand[c] = ((unsigned long long)__float_as_uint(sv) << 32) | (unsigned)tok;
        }
    }
    __syncthreads();
    int ncand = s_ncand;
    int need = KS_ - below;
    for (int c = t; c < ncand; c += 1024) {
        unsigned long long key = cand[c];
        int rank = 0;
        for (int j = 0; j < ncand; j++) rank += (cand[j] < key);
        if (rank < need) {
            int tok = (int)(unsigned)(key & 0xffffffffULL);
            int slot = below + rank;
            g_selidx[b*KS_ + slot] = b*L_ + tok;
            g_selpos[b*L_ + tok] = b*KS_ + slot;
        }
    }
}

// ---------------- K3: coherence-weighted pooling (reads fp16 normed) -------
__global__ void pooled_part_kernel() {
    int b = blockIdx.y, ch = blockIdx.x;
    int d = threadIdx.x;
    float acc = 0.f;
    int l0 = ch * (L_/16);
    for (int l = l0; l < l0 + L_/16; l++)
        acc += g_scores[b*L_ + l] * __half2float(g_nh[((size_t)(b*L_ + l))*D_ + d]);
    g_ppart[(b*16 + ch)*D_ + d] = acc;
}
__global__ void pooled_fin_kernel() {
    int b = blockIdx.x; int d = threadIdx.x;
    float acc = 0.f;
    #pragma unroll
    for (int c = 0; c < 16; c++) acc += g_ppart[(b*16 + c)*D_ + d];
    g_pooled[b*D_ + d] = acc / g_ssum[b];
}
__global__ void pooledwm_kernel(const float* __restrict__ Wm) {
    int b = blockIdx.y;
    int n = blockIdx.x*256 + threadIdx.x;
    float acc = 0.f;
    for (int d = 0; d < D_; d++) acc += g_pooled[b*D_ + d] * Wm[d*D_ + n];
    g_pooledWm[b*D_ + n] = acc;
}

// ---------------- fp16 GEMM: mma m16n8k16, dual ldmatrix, 3-stage ----------
// OUT: 1 = GELU -> fp16 Ch; 4 = raw f32 partial (split-K via gridDim.z);
//      5 = KVM epilogue (K,V -> fp16 g_khf/g_vhf, mix -> f32 g_mixb; + bias).
#define RS_  40                   // smem row stride in halves (80 B)
#define HSTG_ (128*RS_*2)         // bytes per stage per operand = 10240
template<int OUT, bool GATHER>
__global__ __launch_bounds__(128)
void gemm_h(const __half* __restrict__ A, const int* __restrict__ gidx,
            const __half* __restrict__ Bt, const float* __restrict__ bias,
            float* __restrict__ C, __half* __restrict__ Ch, int M, int N, int K) {
    __shared__ __align__(128) __half As[3][128][RS_];
    __shared__ __align__(128) __half Bs[3][128][RS_];
    const int tid = threadIdx.x, lane = tid & 31, wid = tid >> 5;
    const int wm = wid & 1, wn = wid >> 1;
    const int g = lane >> 2, t = lane & 3;
    const int m0 = blockIdx.y * 128, n0 = blockIdx.x * 128;
    const int zk = K / (int)gridDim.z;
    const int z0 = blockIdx.z * zk;

    uint32_t sA = smem_u32(&As[0][0][0]);
    uint32_t sB = smem_u32(&Bs[0][0][0]);

    const __half* asrc[4]; unsigned asz[4]; uint32_t a_dst[4];
    const __half* bsrc[4]; uint32_t b_dst[4];
    #pragma unroll
    for (int j = 0; j < 4; j++) {
        int rl = j*32 + (tid >> 2);
        int ck = (tid & 3) * 8;
        int r = m0 + rl;
        bool v = r < M;
        int gr = v ? (GATHER ? gidx[r] : r) : 0;
        asrc[j]  = A + (size_t)gr*K + z0 + ck;
        asz[j]   = v ? 16u : 0u;
        a_dst[j] = sA + (uint32_t)(rl*RS_ + ck) * 2;
        bsrc[j]  = Bt + (size_t)(n0 + rl)*K + z0 + ck;
        b_dst[j] = sB + (uint32_t)(rl*RS_ + ck) * 2;
    }

    uint32_t a_ld = sA + (uint32_t)((wm*64 + (lane & 7) + ((lane >> 3) & 1)*8)*RS_
                                    + ((lane >> 4) & 1)*8) * 2;
    uint32_t b_ld = sB + (uint32_t)((wn*64 + (lane & 7) + ((lane >> 4) & 1)*8)*RS_
                                    + ((lane >> 3) & 1)*8) * 2;

    float acc[4][8][4] = {};
    const int ntiles = zk >> 5;

    auto issue = [&](int stage, int k0) {
        #pragma unroll
        for (int j = 0; j < 4; j++) cpasync16(a_dst[j] + stage*HSTG_, asrc[j] + k0, asz[j]);
        #pragma unroll
        for (int j = 0; j < 4; j++) cpasync16(b_dst[j] + stage*HSTG_, bsrc[j] + k0, 16u);
        cpcommit();
    };

    issue(0, 0);
    if (ntiles > 1) issue(1, 32);
    for (int it = 0; it < ntiles; it++) {
        int st = it % 3;
        if (it == ntiles - 1) cpwait0(); else cpwait1();
        __syncthreads();
        if (it + 2 < ntiles) issue((it + 2) % 3, (it + 2) << 5);
        #pragma unroll
        for (int kk = 0; kk < 32; kk += 16) {
            uint32_t a[4][4], bb[4][4];
            #pragma unroll
            for (int mt = 0; mt < 4; mt++)
                ldsm4(a[mt], a_ld + st*HSTG_ + mt*(16*RS_*2) + kk*2);
            #pragma unroll
            for (int np = 0; np < 4; np++)
                ldsm4(bb[np], b_ld + st*HSTG_ + np*(16*RS_*2) + kk*2);
            #pragma unroll
            for (int mt = 0; mt < 4; mt++)
                #pragma unroll
                for (int nt = 0; nt < 8; nt++) {
                    uint32_t bf[2] = { bb[nt >> 1][(nt & 1)*2], bb[nt >> 1][(nt & 1)*2 + 1] };
                    mma16n8k16h(acc[mt][nt], a[mt], bf);
                }
        }
        __syncthreads();
    }

    // ---- epilogue ----
    const size_t zout = (OUT == 4) ? (size_t)blockIdx.z * M * N : 0;
    const int seg = n0 / 768;
    #pragma unroll
    for (int mt = 0; mt < 4; mt++) {
        #pragma unroll
        for (int nt = 0; nt < 8; nt++) {
            int n = n0 + wn*64 + nt*8 + t*2;
            float bi0 = (OUT == 4) ? 0.f : bias[n];
            float bi1 = (OUT == 4) ? 0.f : bias[n + 1];
            #pragma unroll
            for (int half = 0; half < 2; half++) {
                int m = m0 + wm*64 + mt*16 + g + half*8;
                if (m < M) {
                    float v0 = acc[mt][nt][half*2 + 0] + bi0;
                    float v1 = acc[mt][nt][half*2 + 1] + bi1;
                    size_t off = (size_t)m * N + n;
                    if (OUT == 1) {
                        v0 = 0.5f * v0 * (1.f + erff(v0 * 0.70710678118654752f));
                        v1 = 0.5f * v1 * (1.f + erff(v1 * 0.70710678118654752f));
                        *reinterpret_cast<__half2*>(Ch + off) = __floats2half2_rn(v0, v1);
                    } else if (OUT == 5) {
                        size_t off2 = (size_t)m * D_ + (n - seg*768);
                        if (seg == 0)
                            *reinterpret_cast<__half2*>(g_khf + off2) = __floats2half2_rn(v0, v1);
                        else if (seg == 1)
                            *reinterpret_cast<__half2*>(g_vhf + off2) = __floats2half2_rn(v0, v1);
                        else {
                            float2 o; o.x = v0; o.y = v1;
                            *(float2*)&g_mixb[off2] = o;
                        }
                    } else {
                        float2 o; o.x = v0; o.y = v1;
                        *(float2*)&C[zout + off] = o;
                    }
                }
            }
        }
    }
}

// finish split-K=QZ_ Q partials -> fp16 qselh (+ bias)
__global__ __launch_bounds__(256) void qfin(const float* __restrict__ bq) {
    int i = blockIdx.x * 256 + threadIdx.x;
    if (i < MSEL_*D_) {
        float acc = 0.f;
        #pragma unroll
        for (int z = 0; z < QZ_; z++) acc += g_fp2[(size_t)z*MSEL_*D_ + i];
        g_qselh[i] = __float2half_rn(acc + bq[i % D_]);
    }
}

// FFN2 finish: out = part0 + part1 + bias + h
__global__ __launch_bounds__(256) void ffn2_fin(const float* __restrict__ bf2,
                                                float* __restrict__ out) {
    int i = blockIdx.x * 256 + threadIdx.x;
    const float4* p0 = (const float4*)g_fp2;
    const float4* p1 = (const float4*)(g_fp2 + (size_t)BL_*D_);
    const float4* ph = (const float4*)g_h;
    float4 a = p0[i], b = p1[i], hh = ph[i];
    float4 bi = ((const float4*)bf2)[i % (D_/4)];
    float4 o;
    o.x = a.x + b.x + hh.x + bi.x;
    o.y = a.y + b.y + hh.y + bi.y;
    o.z = a.z + b.z + hh.z + bi.z;
    o.w = a.w + b.w + hh.w + bi.w;
    ((float4*)out)[i] = o;
}

// ---------------- flash attention, split-KV, fp16 mma, 64-key chunks -------
#define QST_ 72
__global__ __launch_bounds__(128) void flash_attn() {
    const int it = blockIdx.x, bh = blockIdx.y, sp = blockIdx.z;
    const int b = bh / H_, h = bh % H_;
    const int i0 = it * 64;
    __shared__ __align__(128) __half Qh[64][QST_];
    __shared__ __align__(128) __half Kh[64][QST_];
    __shared__ __align__(128) __half Vt[64][QST_];   // dh-major (transposed)
    __shared__ __align__(128) __half Ph[4][16][QST_];
    const int tid = threadIdx.x, lane = tid & 31, w = tid >> 5;
    const int g = lane >> 2, t = lane & 3;

    #pragma unroll
    for (int q = 0; q < 4; q++) {
        int idx = q*128 + tid;
        int r = idx >> 3, c8 = (idx & 7) * 8;
        int i = i0 + r;
        uint4 v = make_uint4(0u, 0u, 0u, 0u);
        if (i < KS_) v = *(const uint4*)&g_qselh[((size_t)(b*KS_ + i))*D_ + h*DH_ + c8];
        *(uint4*)&Qh[r][c8] = v;
    }

    const uint32_t a_ldQ = smem_u32(&Qh[0][0])
        + (uint32_t)((w*16 + (lane & 7) + ((lane >> 3) & 1)*8)*QST_ + ((lane >> 4) & 1)*8) * 2;
    const uint32_t b_ldK = smem_u32(&Kh[0][0])
        + (uint32_t)(((lane & 7) + ((lane >> 4) & 1)*8)*QST_ + ((lane >> 3) & 1)*8) * 2;
    const uint32_t b_ldV = smem_u32(&Vt[0][0])
        + (uint32_t)(((lane & 7) + ((lane >> 4) & 1)*8)*QST_ + ((lane >> 3) & 1)*8) * 2;
    const uint32_t a_ldP = smem_u32(&Ph[w][0][0])
        + (uint32_t)(((lane & 7) + ((lane >> 3) & 1)*8)*QST_ + ((lane >> 4) & 1)*8) * 2;

    float accO[8][4] = {};
    float m0r = -1e30f, m1r = -1e30f, l0r = 0.f, l1r = 0.f;
    __syncthreads();

    for (int j0 = sp * JSEG_; j0 < (sp + 1) * JSEG_; j0 += 64) {
        // K chunk: straight fp16 copy (64 rows x 64 halves)
        #pragma unroll
        for (int q = 0; q < 4; q++) {
            int idx = q*128 + tid;
            int r = idx >> 3, c8 = (idx & 7) * 8;
            *(uint4*)&Kh[r][c8] =
                *(const uint4*)&g_khf[((size_t)(b*L_ + j0 + r))*D_ + h*DH_ + c8];
        }
        // V chunk transposed: Vt[dh][j], fp16 source
        #pragma unroll
        for (int q = 0; q < 4; q++) {
            int idx = q*128 + tid;
            int r = idx & 63, c0 = (idx >> 6) * 8;
            uint4 vv = *(const uint4*)&g_vhf[((size_t)(b*L_ + j0 + r))*D_ + h*DH_ + c0];
            const __half* hp = reinterpret_cast<const __half*>(&vv);
            #pragma unroll
            for (int i = 0; i < 8; i++) Vt[c0 + i][r] = hp[i];
        }
        __syncthreads();

        // S = (Q K^T) * 0.125 ; warp m16 x 64 cols
        float sacc[8][4] = {};
        #pragma unroll
        for (int ks = 0; ks < 4; ks++) {
            uint32_t a[4], bb[4][4];
            ldsm4(a, a_ldQ + ks*32);
            #pragma unroll
            for (int np = 0; np < 4; np++)
                ldsm4(bb[np], b_ldK + np*(16*QST_*2) + ks*32);
            #pragma unroll
            for (int nt = 0; nt < 8; nt++) {
                uint32_t bf[2] = { bb[nt >> 1][(nt & 1)*2], bb[nt >> 1][(nt & 1)*2 + 1] };
                mma16n8k16h(sacc[nt], a, bf);
            }
        }
        float cm0 = -1e30f, cm1 = -1e30f;
        #pragma unroll
        for (int nt = 0; nt < 8; nt++) {
            sacc[nt][0] *= 0.125f; sacc[nt][1] *= 0.125f;
            sacc[nt][2] *= 0.125f; sacc[nt][3] *= 0.125f;
            cm0 = fmaxf(cm0, fmaxf(sacc[nt][0], sacc[nt][1]));
            cm1 = fmaxf(cm1, fmaxf(sacc[nt][2], sacc[nt][3]));
        }
        cm0 = fmaxf(cm0, __shfl_xor_sync(0xffffffffu, cm0, 1));
        cm0 = fmaxf(cm0, __shfl_xor_sync(0xffffffffu, cm0, 2));
        cm1 = fmaxf(cm1, __shfl_xor_sync(0xffffffffu, cm1, 1));
        cm1 = fmaxf(cm1, __shfl_xor_sync(0xffffffffu, cm1, 2));
        float mn0 = fmaxf(m0r, cm0), mn1 = fmaxf(m1r, cm1);
        float al0 = expf(m0r - mn0), al1 = expf(m1r - mn1);
        m0r = mn0; m1r = mn1;
        float s0 = 0.f, s1 = 0.f;
        #pragma unroll
        for (int nt = 0; nt < 8; nt++) {
            float p0 = expf(sacc[nt][0] - mn0);
            float p1 = expf(sacc[nt][1] - mn0);
            float p2 = expf(sacc[nt][2] - mn1);
            float p3 = expf(sacc[nt][3] - mn1);
            s0 += p0 + p1; s1 += p2 + p3;
            int c = nt*8 + t*2;
            *reinterpret_cast<__half2*>(&Ph[w][g][c])     = __floats2half2_rn(p0, p1);
            *reinterpret_cast<__half2*>(&Ph[w][g + 8][c]) = __floats2half2_rn(p2, p3);
        }
        s0 += __shfl_xor_sync(0xffffffffu, s0, 1);
        s0 += __shfl_xor_sync(0xffffffffu, s0, 2);
        s1 += __shfl_xor_sync(0xffffffffu, s1, 1);
        s1 += __shfl_xor_sync(0xffffffffu, s1, 2);
        l0r = l0r*al0 + s0; l1r = l1r*al1 + s1;
        #pragma unroll
        for (int nt = 0; nt < 8; nt++) {
            accO[nt][0] *= al0; accO[nt][1] *= al0;
            accO[nt][2] *= al1; accO[nt][3] *= al1;
        }
        __syncwarp();
        // O += P V   (k = 64 keys, 4 k16 steps; V dh-major B fragments)
        #pragma unroll
        for (int ks = 0; ks < 4; ks++) {
            uint32_t a[4];
            ldsm4(a, a_ldP + ks*32);
            uint32_t bb[4][4];
            #pragma unroll
            for (int np = 0; np < 4; np++)
                ldsm4(bb[np], b_ldV + np*(16*QST_*2) + ks*32);
            #pragma unroll
            for (int nt = 0; nt < 8; nt++) {
                uint32_t bf[2] = { bb[nt >> 1][(nt & 1)*2], bb[nt >> 1][(nt & 1)*2 + 1] };
                mma16n8k16h(accO[nt], a, bf);
            }
        }
        __syncthreads();
    }

    const size_t slot0 = (size_t)(bh*NSPL_ + sp)*320 + it*64 + w*16 + g;
    const size_t slot1 = slot0 + 8;
    if (t == 0) {
        g_pm[slot0] = m0r; g_pl[slot0] = l0r;
        g_pm[slot1] = m1r; g_pl[slot1] = l1r;
    }
    #pragma unroll
    for (int nt = 0; nt < 8; nt++) {
        int c = nt*8 + t*2;
        g_po[slot0*64 + c]     = accO[nt][0];
        g_po[slot0*64 + c + 1] = accO[nt][1];
        g_po[slot1*64 + c]     = accO[nt][2];
        g_po[slot1*64 + c + 1] = accO[nt][3];
    }
}

// combine split-KV partials -> g_ctxh (fp16, feeds Wo GEMM)
__global__ __launch_bounds__(256) void attn_combine() {
    const int it = blockIdx.x, bh = blockIdx.y;
    const int b = bh / H_, h = bh % H_;
    __shared__ float ws[64][NSPL_];
    __shared__ float linv[64];
    const int tid = threadIdx.x;
    if (tid < 64) {
        size_t base = (size_t)(bh*NSPL_)*320 + it*64 + tid;
        float mv[NSPL_]; float m = -1e30f;
        #pragma unroll
        for (int s = 0; s < NSPL_; s++) { mv[s] = g_pm[base + (size_t)s*320]; m = fmaxf(m, mv[s]); }
        float l = 0.f;
        #pragma unroll
        for (int s = 0; s < NSPL_; s++) {
            float wv = expf(mv[s] - m);
            ws[tid][s] = wv;
            l += g_pl[base + (size_t)s*320] * wv;
        }
        linv[tid] = 1.f / l;
    }
    __syncthreads();
    #pragma unroll
    for (int q = 0; q < 16; q++) {
        int idx = q*256 + tid;
        int r = idx >> 6, c = idx & 63;
        int i = it*64 + r;
        if (i < KS_) {
            size_t slot = (size_t)(bh*NSPL_)*320 + it*64 + r;
            float acc = 0.f;
            #pragma unroll
            for (int s = 0; s < NSPL_; s++)
                acc += g_po[(slot + (size_t)s*320)*64 + c] * ws[r][s];
            g_ctxh[((size_t)(b*KS_ + i))*D_ + h*DH_ + c] = __float2half_rn(acc * linv[r]);
        }
    }
}

// ---------------- merge paths (Wo split-K fin fused) + residual + LN2 ------
__global__ void merge_ln2_kernel(const float* __restrict__ x, const float* __restrict__ g2,
                                 const float* __restrict__ b2, const float* __restrict__ bo) {
    int tok = blockIdx.x;
    int b = tok >> 11;
    int t = threadIdx.x;
    int pos = g_selpos[tok];
    float sc = g_scores[tok];
    __shared__ float sh[32];
    float hv[3]; float s = 0.f, sq = 0.f;
    #pragma unroll
    for (int i = 0; i < 3; i++) {
        int d = t + 256*i;
        float mg;
        if (pos >= 0) {
            mg = bo[d];
            size_t base = (size_t)pos*D_ + d;
            #pragma unroll
            for (int z = 0; z < QZ_; z++) mg += g_fp2[(size_t)z*MSEL_*D_ + base];
        } else {
            mg = g_mixb[(size_t)tok*D_ + d] + sc * g_pooledWm[b*D_ + d];
        }
        float u = x[(size_t)tok*D_ + d] + mg;
        hv[i] = u;
        g_h[(size_t)tok*D_ + d] = u;
        s += u; sq += u*u;
    }
    s  = blockReduceSum(s,  sh);
    sq = blockReduceSum(sq, sh);
    float mean = s * (1.f/D_);
    float rstd = rsqrtf(sq*(1.f/D_) - mean*mean + 1e-5f);
    #pragma unroll
    for (int i = 0; i < 3; i++) {
        int d = t + 256*i;
        g_n2h[(size_t)tok*D_ + d] = __float2half_rn((hv[i] - mean) * rstd * g2[d] + b2[d]);
    }
}

// ---------------- host launch ----------------
extern "C" void kernel_launch(void* const* d_in, const int* in_sizes, int n_in,
                              void* d_out, int out_size) {
    (void)in_sizes; (void)n_in; (void)out_size;
    const float* x   = (const float*)d_in[0];
    const float* g1  = (const float*)d_in[1];
    const float* b1  = (const float*)d_in[2];
    const float* g2  = (const float*)d_in[3];
    const float* b2  = (const float*)d_in[4];
    const float* Wr  = (const float*)d_in[5];
    const float* br  = (const float*)d_in[6];
    const float* Wq  = (const float*)d_in[7];
    const float* bq  = (const float*)d_in[8];
    const float* Wk  = (const float*)d_in[9];
    const float* bk  = (const float*)d_in[10];
    const float* Wv  = (const float*)d_in[11];
    const float* bv  = (const float*)d_in[12];
    const float* Wo  = (const float*)d_in[13];
    const float* bo  = (const float*)d_in[14];
    const float* Wm  = (const float*)d_in[15];
    const float* bm  = (const float*)d_in[16];
    const float* W1  = (const float*)d_in[17];
    const float* bf1 = (const float*)d_in[18];
    const float* W2  = (const float*)d_in[19];
    const float* bf2 = (const float*)d_in[20];
    float* out = (float*)d_out;

    float *p_bkvm, *p_fp2;
    __half *p_nh, *p_qselh, *p_ctxh, *p_n2h, *p_th, *p_whuf;
    int* p_selidx;
    cudaGetSymbolAddress((void**)&p_nh,     g_nh);
    cudaGetSymbolAddress((void**)&p_bkvm,   g_bkvm);
    cudaGetSymbolAddress((void**)&p_qselh,  g_qselh);
    cudaGetSymbolAddress((void**)&p_ctxh,   g_ctxh);
    cudaGetSymbolAddress((void**)&p_n2h,    g_n2h);
    cudaGetSymbolAddress((void**)&p_th,     g_th);
    cudaGetSymbolAddress((void**)&p_whuf,   g_whuf);
    cudaGetSymbolAddress((void**)&p_selidx, g_selidx);
    cudaGetSymbolAddress((void**)&p_fp2,    g_fp2);

    __half* rKVM = p_whuf;                         // [2304][768]
    __half* rWq  = p_whuf + 3*(size_t)WSZ_;
    __half* rWo  = p_whuf + 4*(size_t)WSZ_;
    __half* rW1  = p_whuf + 5*(size_t)WSZ_;
    __half* rW2  = rW1 + (size_t)W1SZ_;

    // 0. fused weight prep (single launch)
    TP7 tp;
    tp.in[0]=Wk; tp.out[0]=rKVM + 0*(size_t)WSZ_; tp.K[0]=D_; tp.N[0]=D_;
    tp.in[1]=Wv; tp.out[1]=rKVM + 1*(size_t)WSZ_; tp.K[1]=D_; tp.N[1]=D_;
    tp.in[2]=Wm; tp.out[2]=rKVM + 2*(size_t)WSZ_; tp.K[2]=D_; tp.N[2]=D_;
    tp.in[3]=Wq; tp.out[3]=rWq;                   tp.K[3]=D_; tp.N[3]=D_;
    tp.in[4]=Wo; tp.out[4]=rWo;                   tp.K[4]=D_; tp.N[4]=D_;
    tp.in[5]=W1; tp.out[5]=rW1;                   tp.K[5]=D_; tp.N[5]=F_;
    tp.in[6]=W2; tp.out[6]=rW2;                   tp.K[6]=F_; tp.N[6]=D_;
    int total = 0;
    for (int s = 0; s < 7; s++) {
        tp.cum[s] = total;
        total += (tp.K[s]/64) * (tp.N[s]/32);
    }
    tp.cum[7] = total;
    transpose_all_kernel<<<total, dim3(32, 8)>>>(tp);
    bias_concat_kernel<<<9, 256>>>(bk, bv, bm);
    // 1. LN1 + router
    ln1_router_kernel<<<BL_, 256>>>(x, g1, b1, Wr, br);
    // 2. top-k (histogram select + rank counting)
    topk_kernel<<<B_, 1024>>>();
    // 3. pooling path
    pooled_part_kernel<<<dim3(16, B_), D_>>>();
    pooled_fin_kernel<<<B_, D_>>>();
    pooledwm_kernel<<<dim3(3, B_), 256>>>(Wm);
    // 4. fused K|V|mix projection (N=2304): K,V -> fp16, mix -> f32
    gemm_h<5,false><<<dim3(NKVM_/128, BL_/128), 128>>>(p_nh, nullptr, rKVM, p_bkvm, nullptr, nullptr, BL_, NKVM_, D_);
    // 5. Q for selected rows (gather, split-K=4) -> fin -> fp16
    gemm_h<4,true ><<<dim3(D_/128, (MSEL_+127)/128, QZ_), 128>>>(p_nh, p_selidx, rWq, nullptr, p_fp2, nullptr, MSEL_, D_, D_);
    qfin<<<(MSEL_*D_ + 255)/256, 256>>>(bq);
    // 6. flash attention (split-KV, 64-key chunks) + combine
    flash_attn<<<dim3(5, B_*H_, NSPL_), 128>>>();
    attn_combine<<<dim3(5, B_*H_), 256>>>();
    // Wo projection (split-K=4): partials consumed directly by merge_ln2
    gemm_h<4,false><<<dim3(D_/128, (MSEL_+127)/128, QZ_), 128>>>(p_ctxh, nullptr, rWo, nullptr, p_fp2, nullptr, MSEL_, D_, D_);
    // 7. merge (Wo fin fused) + residual + LN2
    merge_ln2_kernel<<<BL_, 256>>>(x, g2, b2, bo);
    // 8. FFN: FFN1 GELU -> fp16; FFN2 split-K=2 -> partials -> fin(out)
    gemm_h<1,false><<<dim3(F_/128, BL_/128), 128>>>(p_n2h, nullptr, rW1, bf1, nullptr, p_th, BL_, F_, D_);
    gemm_h<4,false><<<dim3(D_/128, BL_/128, 2), 128>>>(p_th, nullptr, rW2, nullptr, p_fp2, nullptr, BL_, D_, F_);
    ffn2_fin<<<(BL_*D_/4)/256, 256>>>(bf2, out);
}

// round 15
// speedup vs baseline: 1.0349x; 1.0349x over previous
#include <cuda_runtime.h>
#include <cuda_fp16.h>
#include <math.h>
#include <stdint.h>

// Problem constants
#define B_    4
#define L_    2048
#define D_    768
#define H_    12
#define DH_   64
#define F_    3072
#define KS_   307              // round(0.15 * 2048)
#define BL_   (B_*L_)          // 8192
#define MSEL_ (B_*KS_)         // 1228
#define NKVM_ 2304             // 3*D concat (K,V,M)
#define NSPL_ 4                // KV splits in flash attention
#define JSEG_ (L_/NSPL_)       // 512
#define QZ_   4                // split-K for Q/Wo GEMMs

#define WSZ_  589824           // 768*768
#define W1SZ_ 2359296          // 768*3072

// ---------------- scratch (static device globals; allocation-free) ----------
__device__ __align__(16) __half g_nh[BL_*(size_t)D_];   // fp16 LN1 output
__device__ float g_scores[BL_];
__device__ float g_ssum[B_];
__device__ int   g_selidx[MSEL_];
__device__ int   g_selpos[BL_];
__device__ float g_ppart[B_*16*D_];
__device__ float g_pooledWm[B_*D_];
__device__ __align__(16) __half g_khf[BL_*(size_t)D_];  // fp16 K
__device__ __align__(16) __half g_vhf[BL_*(size_t)D_];  // fp16 V
__device__ float g_mixb[BL_*(size_t)D_];                // fp32 mix base
__device__ float g_bkvm[NKVM_];
__device__ __align__(16) __half g_qselh[MSEL_*(size_t)D_];
__device__ float g_po[(size_t)B_*H_*NSPL_*320*64];   // attention partial O
__device__ float g_pm[B_*H_*NSPL_*320];
__device__ float g_pl[B_*H_*NSPL_*320];
__device__ __align__(16) __half g_ctxh[MSEL_*(size_t)D_];
__device__ float g_h[BL_*(size_t)D_];
__device__ __align__(16) __half g_n2h[BL_*(size_t)D_];
__device__ __align__(16) __half g_th[BL_*(size_t)F_];
__device__ float g_fp2[2*(size_t)BL_*D_];     // split-K partials (reused: Q, Wo, FFN2)
__device__ __align__(16) __half g_whuf[5*(size_t)WSZ_ + 2*(size_t)W1SZ_];  // fp16 [N][K] weights

// ---------------- small helpers ----------------
__device__ __forceinline__ uint32_t smem_u32(const void* p) {
    uint32_t a;
    asm("{ .reg .u64 t; cvta.to.shared.u64 t, %1; cvt.u32.u64 %0, t; }"
        : "=r"(a) : "l"(p));
    return a;
}
__device__ __forceinline__ void mma16n8k16h(float* c, const uint32_t* a, const uint32_t* b) {
    asm volatile(
        "mma.sync.aligned.m16n8k16.row.col.f32.f16.f16.f32 "
        "{%0,%1,%2,%3}, {%4,%5,%6,%7}, {%8,%9}, {%0,%1,%2,%3};"
        : "+f"(c[0]), "+f"(c[1]), "+f"(c[2]), "+f"(c[3])
        : "r"(a[0]), "r"(a[1]), "r"(a[2]), "r"(a[3]), "r"(b[0]), "r"(b[1]));
}
__device__ __forceinline__ void ldsm4(uint32_t* r, uint32_t addr) {
    asm volatile("ldmatrix.sync.aligned.m8n8.x4.shared.b16 {%0,%1,%2,%3}, [%4];"
        : "=r"(r[0]), "=r"(r[1]), "=r"(r[2]), "=r"(r[3]) : "r"(addr));
}
__device__ __forceinline__ void cpasync16(uint32_t dst, const void* src, unsigned sz) {
    asm volatile("cp.async.cg.shared.global [%0], [%1], 16, %2;"
        :: "r"(dst), "l"(src), "r"(sz));
}
__device__ __forceinline__ void cpcommit() { asm volatile("cp.async.commit_group;"); }
__device__ __forceinline__ void cpwait0()  { asm volatile("cp.async.wait_group 0;"); }
__device__ __forceinline__ void cpwait1()  { asm volatile("cp.async.wait_group 1;"); }

// ---------------- reductions ----------------
__device__ __forceinline__ float blockReduceSum(float v, float* sh) {
    __syncthreads();
    int lane = threadIdx.x & 31, w = threadIdx.x >> 5;
    #pragma unroll
    for (int o = 16; o > 0; o >>= 1) v += __shfl_xor_sync(0xffffffffu, v, o);
    if (lane == 0) sh[w] = v;
    __syncthreads();
    int nw = (blockDim.x + 31) >> 5;
    if (w == 0) {
        v = (lane < nw) ? sh[lane] : 0.f;
        #pragma unroll
        for (int o = 16; o > 0; o >>= 1) v += __shfl_xor_sync(0xffffffffu, v, o);
        if (lane == 0) sh[0] = v;
    }
    __syncthreads();
    return sh[0];
}

// ---------------- W prep: fused 7-way transpose [K][N] fp32 -> [N][K] fp16 --
struct TP7 {
    const float* in[7];
    __half* out[7];
    int K[7], N[7];
    int cum[8];
};
__global__ void transpose_all_kernel(TP7 p) {
    __shared__ float tile[64][33];
    int flat = blockIdx.x;
    int s = 0;
    #pragma unroll
    for (int i = 1; i < 7; i++) s += (flat >= p.cum[i]);
    int id = flat - p.cum[s];
    int K = p.K[s], N = p.N[s];
    int ntl = N >> 5;
    int k0 = (id / ntl) * 64, n0 = (id % ntl) * 32;
    const float* in = p.in[s];
    __half* out = p.out[s];
    int tx = threadIdx.x, ty = threadIdx.y;   // (32, 8)
    #pragma unroll
    for (int i = 0; i < 64; i += 8)
        tile[ty + i][tx] = in[(size_t)(k0 + ty + i) * N + n0 + tx];
    __syncthreads();
    #pragma unroll
    for (int i = 0; i < 32; i += 8) {
        int n = n0 + ty + i;
        __half2 v = __floats2half2_rn(tile[tx*2][ty + i], tile[tx*2 + 1][ty + i]);
        *reinterpret_cast<__half2*>(&out[(size_t)n * K + k0 + tx*2]) = v;
    }
}

__global__ void bias_concat_kernel(const float* __restrict__ bk, const float* __restrict__ bv,
                                   const float* __restrict__ bm) {
    int d = blockIdx.x * 256 + threadIdx.x;
    float v = (d < 768) ? bk[d] : ((d < 1536) ? bv[d - 768] : bm[d - 1536]);
    g_bkvm[d] = v;
}

// ---------------- K1: LN1 + router score ----------------
__global__ void ln1_router_kernel(const float* __restrict__ x, const float* __restrict__ g1,
                                  const float* __restrict__ b1, const float* __restrict__ Wr,
                                  const float* __restrict__ br) {
    int tok = blockIdx.x;
    int t = threadIdx.x;   // 256
    const float* xr = x + (size_t)tok * D_;
    __shared__ float sh[32];
    float v[3]; float s = 0.f, sq = 0.f;
    #pragma unroll
    for (int i = 0; i < 3; i++) { float u = xr[t + 256*i]; v[i] = u; s += u; sq += u*u; }
    s  = blockReduceSum(s,  sh);
    sq = blockReduceSum(sq, sh);
    float mean = s * (1.f/D_);
    float var  = sq * (1.f/D_) - mean*mean;
    float rstd = rsqrtf(var + 1e-5f);
    float dot = 0.f;
    #pragma unroll
    for (int i = 0; i < 3; i++) {
        int d = t + 256*i;
        float nv = (v[i] - mean) * rstd * g1[d] + b1[d];
        g_nh[(size_t)tok*D_ + d] = __float2half_rn(nv);
        dot += nv * Wr[d];
    }
    dot = blockReduceSum(dot, sh);
    if (t == 0) g_scores[tok] = 1.f / (1.f + expf(-(dot + br[0])));
}

// ---------------- K2: exact top-k via histogram select + rank counting -----
__global__ void topk_kernel() {
    int b = blockIdx.x, t = threadIdx.x;   // 1024 threads
    __shared__ int hist[2048];
    __shared__ unsigned long long cand[2048];
    __shared__ float sh[32];
    __shared__ int wsum[32];
    __shared__ int s_thr, s_below, s_ncand, s_ndir;
    hist[t] = 0; hist[t + 1024] = 0;
    if (t == 0) { s_ncand = 0; s_ndir = 0; }
    float s0 = g_scores[b*L_ + t];
    float s1 = g_scores[b*L_ + t + 1024];
    g_selpos[b*L_ + t] = -1;
    g_selpos[b*L_ + t + 1024] = -1;
    float tot = blockReduceSum(s0 + s1, sh);
    if (t == 0) g_ssum[b] = tot + 1e-6f;
    __syncthreads();
    unsigned u0 = __float_as_uint(s0) >> 21;
    unsigned u1 = __float_as_uint(s1) >> 21;
    atomicAdd(&hist[u0], 1);
    atomicAdd(&hist[u1], 1);
    __syncthreads();
    int h0 = hist[2*t], h1 = hist[2*t + 1];
    int pair = h0 + h1;
    int lane = t & 31, wrp = t >> 5;
    int v = pair;
    #pragma unroll
    for (int o = 1; o < 32; o <<= 1) {
        int u = __shfl_up_sync(0xffffffffu, v, o);
        if (lane >= o) v += u;
    }
    if (lane == 31) wsum[wrp] = v;
    __syncthreads();
    if (wrp == 0) {
        int u = wsum[lane];
        #pragma unroll
        for (int o = 1; o < 32; o <<= 1) {
            int z = __shfl_up_sync(0xffffffffu, u, o);
            if (lane >= o) u += z;
        }
        wsum[lane] = u;
    }
    __syncthreads();
    int incl_pair = v + (wrp ? wsum[wrp - 1] : 0);
    int excl = incl_pair - pair;
    int incl0 = excl + h0;
    if (incl0 >= KS_ && excl < KS_)       { s_thr = 2*t;     s_below = excl; }
    if (incl_pair >= KS_ && incl0 < KS_)  { s_thr = 2*t + 1; s_below = incl0; }
    __syncthreads();
    const int thr = s_thr, below = s_below;
    #pragma unroll
    for (int q = 0; q < 2; q++) {
        int tok = t + q*1024;
        float sv = q ? s1 : s0;
        unsigned uv = q ? u1 : u0;
        if ((int)uv < thr) {
            int slot = atomicAdd(&s_ndir, 1);
            g_selidx[b*KS_ + slot] = b*L_ + tok;
            g_selpos[b*L_ + tok] = b*KS_ + slot;
        } else if ((int)uv == thr) {
            int c = atomicAdd(&s_ncand, 1);
            cand[c] = ((unsigned long long)__float_as_uint(sv) << 32) | (unsigned)tok;
        }
    }
    __syncthreads();
    int ncand = s_ncand;
    int need = KS_ - below;
    for (int c = t; c < ncand; c += 1024) {
        unsigned long long key = cand[c];
        int rank = 0;
        for (int j = 0; j < ncand; j++) rank += (cand[j] < key);
        if (rank < need) {
            int tok = (int)(unsigned)(key & 0xffffffffULL);
            int slot = below + rank;
            g_selidx[b*KS_ + slot] = b*L_ + tok;
            g_selpos[b*L_ + tok] = b*KS_ + slot;
        }
    }
}

// ---------------- K3: coherence-weighted pooling (reads fp16 normed) -------
__global__ void pooled_part_kernel() {
    int b = blockIdx.y, ch = blockIdx.x;
    int d = threadIdx.x;
    float acc = 0.f;
    int l0 = ch * (L_/16);
    for (int l = l0; l < l0 + L_/16; l++)
        acc += g_scores[b*L_ + l] * __half2float(g_nh[((size_t)(b*L_ + l))*D_ + d]);
    g_ppart[(b*16 + ch)*D_ + d] = acc;
}
// fused: pooled_fin + pooled@Wm  (g_pooled was single-consumer)
__global__ void pooledwm_kernel(const float* __restrict__ Wm) {
    int b = blockIdx.y;
    __shared__ float pooled_s[D_];
    int tid = threadIdx.x;   // 256
    float sv = g_ssum[b];
    for (int d = tid; d < D_; d += 256) {
        float acc = 0.f;
        #pragma unroll
        for (int c = 0; c < 16; c++) acc += g_ppart[(b*16 + c)*D_ + d];
        pooled_s[d] = acc / sv;
    }
    __syncthreads();
    int n = blockIdx.x*256 + tid;
    float acc = 0.f;
    for (int d = 0; d < D_; d++) acc += pooled_s[d] * Wm[d*D_ + n];
    g_pooledWm[b*D_ + n] = acc;
}

// ---------------- fp16 GEMM: mma m16n8k16, dual ldmatrix, 3-stage ----------
// OUT: 1 = GELU -> fp16 Ch; 4 = raw f32 partial (split-K via gridDim.z);
//      5 = KVM epilogue (K,V -> fp16 g_khf/g_vhf, mix -> f32 g_mixb; + bias).
#define RS_  40                   // smem row stride in halves (80 B)
#define HSTG_ (128*RS_*2)         // bytes per stage per operand = 10240
template<int OUT, bool GATHER>
__global__ __launch_bounds__(128)
void gemm_h(const __half* __restrict__ A, const int* __restrict__ gidx,
            const __half* __restrict__ Bt, const float* __restrict__ bias,
            float* __restrict__ C, __half* __restrict__ Ch, int M, int N, int K) {
    __shared__ __align__(128) __half As[3][128][RS_];
    __shared__ __align__(128) __half Bs[3][128][RS_];
    const int tid = threadIdx.x, lane = tid & 31, wid = tid >> 5;
    const int wm = wid & 1, wn = wid >> 1;
    const int g = lane >> 2, t = lane & 3;
    const int m0 = blockIdx.y * 128, n0 = blockIdx.x * 128;
    const int zk = K / (int)gridDim.z;
    const int z0 = blockIdx.z * zk;

    uint32_t sA = smem_u32(&As[0][0][0]);
    uint32_t sB = smem_u32(&Bs[0][0][0]);

    const __half* asrc[4]; unsigned asz[4]; uint32_t a_dst[4];
    const __half* bsrc[4]; uint32_t b_dst[4];
    #pragma unroll
    for (int j = 0; j < 4; j++) {
        int rl = j*32 + (tid >> 2);
        int ck = (tid & 3) * 8;
        int r = m0 + rl;
        bool v = r < M;
        int gr = v ? (GATHER ? gidx[r] : r) : 0;
        asrc[j]  = A + (size_t)gr*K + z0 + ck;
        asz[j]   = v ? 16u : 0u;
        a_dst[j] = sA + (uint32_t)(rl*RS_ + ck) * 2;
        bsrc[j]  = Bt + (size_t)(n0 + rl)*K + z0 + ck;
        b_dst[j] = sB + (uint32_t)(rl*RS_ + ck) * 2;
    }

    uint32_t a_ld = sA + (uint32_t)((wm*64 + (lane & 7) + ((lane >> 3) & 1)*8)*RS_
                                    + ((lane >> 4) & 1)*8) * 2;
    uint32_t b_ld = sB + (uint32_t)((wn*64 + (lane & 7) + ((lane >> 4) & 1)*8)*RS_
                                    + ((lane >> 3) & 1)*8) * 2;

    float acc[4][8][4] = {};
    const int ntiles = zk >> 5;

    auto issue = [&](int stage, int k0) {
        #pragma unroll
        for (int j = 0; j < 4; j++) cpasync16(a_dst[j] + stage*HSTG_, asrc[j] + k0, asz[j]);
        #pragma unroll
        for (int j = 0; j < 4; j++) cpasync16(b_dst[j] + stage*HSTG_, bsrc[j] + k0, 16u);
        cpcommit();
    };

    issue(0, 0);
    if (ntiles > 1) issue(1, 32);
    for (int it = 0; it < ntiles; it++) {
        int st = it % 3;
        if (it == ntiles - 1) cpwait0(); else cpwait1();
        __syncthreads();
        if (it + 2 < ntiles) issue((it + 2) % 3, (it + 2) << 5);
        #pragma unroll
        for (int kk = 0; kk < 32; kk += 16) {
            uint32_t a[4][4], bb[4][4];
            #pragma unroll
            for (int mt = 0; mt < 4; mt++)
                ldsm4(a[mt], a_ld + st*HSTG_ + mt*(16*RS_*2) + kk*2);
            #pragma unroll
            for (int np = 0; np < 4; np++)
                ldsm4(bb[np], b_ld + st*HSTG_ + np*(16*RS_*2) + kk*2);
            #pragma unroll
            for (int mt = 0; mt < 4; mt++)
                #pragma unroll
                for (int nt = 0; nt < 8; nt++) {
                    uint32_t bf[2] = { bb[nt >> 1][(nt & 1)*2], bb[nt >> 1][(nt & 1)*2 + 1] };
                    mma16n8k16h(acc[mt][nt], a[mt], bf);
                }
        }
        __syncthreads();
    }

    // ---- epilogue ----
    const size_t zout = (OUT == 4) ? (size_t)blockIdx.z * M * N : 0;
    const int seg = n0 / 768;
    #pragma unroll
    for (int mt = 0; mt < 4; mt++) {
        #pragma unroll
        for (int nt = 0; nt < 8; nt++) {
            int n = n0 + wn*64 + nt*8 + t*2;
            float bi0 = (OUT == 4) ? 0.f : bias[n];
            float bi1 = (OUT == 4) ? 0.f : bias[n + 1];
            #pragma unroll
            for (int half = 0; half < 2; half++) {
                int m = m0 + wm*64 + mt*16 + g + half*8;
                if (m < M) {
                    float v0 = acc[mt][nt][half*2 + 0] + bi0;
                    float v1 = acc[mt][nt][half*2 + 1] + bi1;
                    size_t off = (size_t)m * N + n;
                    if (OUT == 1) {
                        v0 = 0.5f * v0 * (1.f + erff(v0 * 0.70710678118654752f));
                        v1 = 0.5f * v1 * (1.f + erff(v1 * 0.70710678118654752f));
                        *reinterpret_cast<__half2*>(Ch + off) = __floats2half2_rn(v0, v1);
                    } else if (OUT == 5) {
                        size_t off2 = (size_t)m * D_ + (n - seg*768);
                        if (seg == 0)
                            *reinterpret_cast<__half2*>(g_khf + off2) = __floats2half2_rn(v0, v1);
                        else if (seg == 1)
                            *reinterpret_cast<__half2*>(g_vhf + off2) = __floats2half2_rn(v0, v1);
                        else {
                            float2 o; o.x = v0; o.y = v1;
                            *(float2*)&g_mixb[off2] = o;
                        }
                    } else {
                        float2 o; o.x = v0; o.y = v1;
                        *(float2*)&C[zout + off] = o;
                    }
                }
            }
        }
    }
}

// finish split-K=QZ_ Q partials -> fp16 qselh (+ bias)
__global__ __launch_bounds__(256) void qfin(const float* __restrict__ bq) {
    int i = blockIdx.x * 256 + threadIdx.x;
    if (i < MSEL_*D_) {
        float acc = 0.f;
        #pragma unroll
        for (int z = 0; z < QZ_; z++) acc += g_fp2[(size_t)z*MSEL_*D_ + i];
        g_qselh[i] = __float2half_rn(acc + bq[i % D_]);
    }
}

// FFN2 finish: out = part0 + part1 + bias + h
__global__ __launch_bounds__(256) void ffn2_fin(const float* __restrict__ bf2,
                                                float* __restrict__ out) {
    int i = blockIdx.x * 256 + threadIdx.x;
    const float4* p0 = (const float4*)g_fp2;
    const float4* p1 = (const float4*)(g_fp2 + (size_t)BL_*D_);
    const float4* ph = (const float4*)g_h;
    float4 a = p0[i], b = p1[i], hh = ph[i];
    float4 bi = ((const float4*)bf2)[i % (D_/4)];
    float4 o;
    o.x = a.x + b.x + hh.x + bi.x;
    o.y = a.y + b.y + hh.y + bi.y;
    o.z = a.z + b.z + hh.z + bi.z;
    o.w = a.w + b.w + hh.w + bi.w;
    ((float4*)out)[i] = o;
}

// ---------------- flash attention, split-KV, fp16 mma, 32-key chunks (R13) -
#define QST_ 72
#define VST_ 40
__global__ __launch_bounds__(128) void flash_attn() {
    const int it = blockIdx.x, bh = blockIdx.y, sp = blockIdx.z;
    const int b = bh / H_, h = bh % H_;
    const int i0 = it * 64;
    __shared__ __align__(128) __half Qh[64][QST_];
    __shared__ __align__(128) __half Kh[32][QST_];
    __shared__ __align__(128) __half Vt[64][VST_];
    __shared__ __align__(128) __half Ph[4][16][VST_];
    const int tid = threadIdx.x, lane = tid & 31, w = tid >> 5;
    const int g = lane >> 2, t = lane & 3;

    #pragma unroll
    for (int q = 0; q < 4; q++) {
        int idx = q*128 + tid;
        int r = idx >> 3, c8 = (idx & 7) * 8;
        int i = i0 + r;
        uint4 v = make_uint4(0u, 0u, 0u, 0u);
        if (i < KS_) v = *(const uint4*)&g_qselh[((size_t)(b*KS_ + i))*D_ + h*DH_ + c8];
        *(uint4*)&Qh[r][c8] = v;
    }

    const uint32_t a_ldQ = smem_u32(&Qh[0][0])
        + (uint32_t)((w*16 + (lane & 7) + ((lane >> 3) & 1)*8)*QST_ + ((lane >> 4) & 1)*8) * 2;
    const uint32_t b_ldK = smem_u32(&Kh[0][0])
        + (uint32_t)(((lane & 7) + ((lane >> 4) & 1)*8)*QST_ + ((lane >> 3) & 1)*8) * 2;
    const uint32_t b_ldV = smem_u32(&Vt[0][0])
        + (uint32_t)(((lane & 7) + ((lane >> 4) & 1)*8)*VST_ + ((lane >> 3) & 1)*8) * 2;
    const uint32_t a_ldP = smem_u32(&Ph[w][0][0])
        + (uint32_t)(((lane & 7) + ((lane >> 3) & 1)*8)*VST_ + ((lane >> 4) & 1)*8) * 2;

    float accO[8][4] = {};
    float m0r = -1e30f, m1r = -1e30f, l0r = 0.f, l1r = 0.f;
    __syncthreads();

    for (int j0 = sp * JSEG_; j0 < (sp + 1) * JSEG_; j0 += 32) {
        // K chunk: straight fp16 copy (32 rows x 64 halves)
        #pragma unroll
        for (int q = 0; q < 2; q++) {
            int idx = q*128 + tid;
            int r = idx >> 3, c8 = (idx & 7) * 8;
            *(uint4*)&Kh[r][c8] =
                *(const uint4*)&g_khf[((size_t)(b*L_ + j0 + r))*D_ + h*DH_ + c8];
        }
        // V chunk transposed: Vt[dh][j], fp16 source
        #pragma unroll
        for (int q = 0; q < 2; q++) {
            int idx = q*128 + tid;
            int r = idx & 31, c0 = (idx >> 5) * 8;
            uint4 vv = *(const uint4*)&g_vhf[((size_t)(b*L_ + j0 + r))*D_ + h*DH_ + c0];
            const __half* hp = reinterpret_cast<const __half*>(&vv);
            #pragma unroll
            for (int i = 0; i < 8; i++) Vt[c0 + i][r] = hp[i];
        }
        __syncthreads();

        float sacc[4][4] = {};
        #pragma unroll
        for (int ks = 0; ks < 4; ks++) {
            uint32_t a[4], bb[2][4];
            ldsm4(a, a_ldQ + ks*32);
            ldsm4(bb[0], b_ldK + ks*32);
            ldsm4(bb[1], b_ldK + 16*QST_*2 + ks*32);
            #pragma unroll
            for (int nt = 0; nt < 4; nt++) {
                uint32_t bf[2] = { bb[nt >> 1][(nt & 1)*2], bb[nt >> 1][(nt & 1)*2 + 1] };
                mma16n8k16h(sacc[nt], a, bf);
            }
        }
        float cm0 = -1e30f, cm1 = -1e30f;
        #pragma unroll
        for (int nt = 0; nt < 4; nt++) {
            sacc[nt][0] *= 0.125f; sacc[nt][1] *= 0.125f;
            sacc[nt][2] *= 0.125f; sacc[nt][3] *= 0.125f;
            cm0 = fmaxf(cm0, fmaxf(sacc[nt][0], sacc[nt][1]));
            cm1 = fmaxf(cm1, fmaxf(sacc[nt][2], sacc[nt][3]));
        }
        cm0 = fmaxf(cm0, __shfl_xor_sync(0xffffffffu, cm0, 1));
        cm0 = fmaxf(cm0, __shfl_xor_sync(0xffffffffu, cm0, 2));
        cm1 = fmaxf(cm1, __shfl_xor_sync(0xffffffffu, cm1, 1));
        cm1 = fmaxf(cm1, __shfl_xor_sync(0xffffffffu, cm1, 2));
        float mn0 = fmaxf(m0r, cm0), mn1 = fmaxf(m1r, cm1);
        float al0 = expf(m0r - mn0), al1 = expf(m1r - mn1);
        m0r = mn0; m1r = mn1;
        float s0 = 0.f, s1 = 0.f;
        #pragma unroll
        for (int nt = 0; nt < 4; nt++) {
            float p0 = expf(sacc[nt][0] - mn0);
            float p1 = expf(sacc[nt][1] - mn0);
            float p2 = expf(sacc[nt][2] - mn1);
            float p3 = expf(sacc[nt][3] - mn1);
            s0 += p0 + p1; s1 += p2 + p3;
            int c = nt*8 + t*2;
            *reinterpret_cast<__half2*>(&Ph[w][g][c])     = __floats2half2_rn(p0, p1);
            *reinterpret_cast<__half2*>(&Ph[w][g + 8][c]) = __floats2half2_rn(p2, p3);
        }
        s0 += __shfl_xor_sync(0xffffffffu, s0, 1);
        s0 += __shfl_xor_sync(0xffffffffu, s0, 2);
        s1 += __shfl_xor_sync(0xffffffffu, s1, 1);
        s1 += __shfl_xor_sync(0xffffffffu, s1, 2);
        l0r = l0r*al0 + s0; l1r = l1r*al1 + s1;
        #pragma unroll
        for (int nt = 0; nt < 8; nt++) {
            accO[nt][0] *= al0; accO[nt][1] *= al0;
            accO[nt][2] *= al1; accO[nt][3] *= al1;
        }
        __syncwarp();
        #pragma unroll
        for (int ks = 0; ks < 2; ks++) {
            uint32_t a[4];
            ldsm4(a, a_ldP + ks*32);
            uint32_t bb[4][4];
            #pragma unroll
            for (int np = 0; np < 4; np++)
                ldsm4(bb[np], b_ldV + np*(16*VST_*2) + ks*32);
            #pragma unroll
            for (int nt = 0; nt < 8; nt++) {
                uint32_t bf[2] = { bb[nt >> 1][(nt & 1)*2], bb[nt >> 1][(nt & 1)*2 + 1] };
                mma16n8k16h(accO[nt], a, bf);
            }
        }
        __syncthreads();
    }

    const size_t slot0 = (size_t)(bh*NSPL_ + sp)*320 + it*64 + w*16 + g;
    const size_t slot1 = slot0 + 8;
    if (t == 0) {
        g_pm[slot0] = m0r; g_pl[slot0] = l0r;
        g_pm[slot1] = m1r; g_pl[slot1] = l1r;
    }
    #pragma unroll
    for (int nt = 0; nt < 8; nt++) {
        int c = nt*8 + t*2;
        g_po[slot0*64 + c]     = accO[nt][0];
        g_po[slot0*64 + c + 1] = accO[nt][1];
        g_po[slot1*64 + c]     = accO[nt][2];
        g_po[slot1*64 + c + 1] = accO[nt][3];
    }
}

// combine split-KV partials -> g_ctxh (fp16, feeds Wo GEMM)
__global__ __launch_bounds__(256) void attn_combine() {
    const int it = blockIdx.x, bh = blockIdx.y;
    const int b = bh / H_, h = bh % H_;
    __shared__ float ws[64][NSPL_];
    __shared__ float linv[64];
    const int tid = threadIdx.x;
    if (tid < 64) {
        size_t base = (size_t)(bh*NSPL_)*320 + it*64 + tid;
        float mv[NSPL_]; float m = -1e30f;
        #pragma unroll
        for (int s = 0; s < NSPL_; s++) { mv[s] = g_pm[base + (size_t)s*320]; m = fmaxf(m, mv[s]); }
        float l = 0.f;
        #pragma unroll
        for (int s = 0; s < NSPL_; s++) {
            float wv = expf(mv[s] - m);
            ws[tid][s] = wv;
            l += g_pl[base + (size_t)s*320] * wv;
        }
        linv[tid] = 1.f / l;
    }
    __syncthreads();
    #pragma unroll
    for (int q = 0; q < 16; q++) {
        int idx = q*256 + tid;
        int r = idx >> 6, c = idx & 63;
        int i = it*64 + r;
        if (i < KS_) {
            size_t slot = (size_t)(bh*NSPL_)*320 + it*64 + r;
            float acc = 0.f;
            #pragma unroll
            for (int s = 0; s < NSPL_; s++)
                acc += g_po[(slot + (size_t)s*320)*64 + c] * ws[r][s];
            g_ctxh[((size_t)(b*KS_ + i))*D_ + h*DH_ + c] = __float2half_rn(acc * linv[r]);
        }
    }
}

// ---------------- merge paths (Wo split-K fin fused) + residual + LN2 ------
__global__ void merge_ln2_kernel(const float* __restrict__ x, const float* __restrict__ g2,
                                 const float* __restrict__ b2, const float* __restrict__ bo) {
    int tok = blockIdx.x;
    int b = tok >> 11;
    int t = threadIdx.x;
    int pos = g_selpos[tok];
    float sc = g_scores[tok];
    __shared__ float sh[32];
    float hv[3]; float s = 0.f, sq = 0.f;
    #pragma unroll
    for (int i = 0; i < 3; i++) {
        int d = t + 256*i;
        float mg;
        if (pos >= 0) {
            mg = bo[d];
            size_t base = (size_t)pos*D_ + d;
            #pragma unroll
            for (int z = 0; z < QZ_; z++) mg += g_fp2[(size_t)z*MSEL_*D_ + base];
        } else {
            mg = g_mixb[(size_t)tok*D_ + d] + sc * g_pooledWm[b*D_ + d];
        }
        float u = x[(size_t)tok*D_ + d] + mg;
        hv[i] = u;
        g_h[(size_t)tok*D_ + d] = u;
        s += u; sq += u*u;
    }
    s  = blockReduceSum(s,  sh);
    sq = blockReduceSum(sq, sh);
    float mean = s * (1.f/D_);
    float rstd = rsqrtf(sq*(1.f/D_) - mean*mean + 1e-5f);
    #pragma unroll
    for (int i = 0; i < 3; i++) {
        int d = t + 256*i;
        g_n2h[(size_t)tok*D_ + d] = __float2half_rn((hv[i] - mean) * rstd * g2[d] + b2[d]);
    }
}

// ---------------- host launch ----------------
extern "C" void kernel_launch(void* const* d_in, const int* in_sizes, int n_in,
                              void* d_out, int out_size) {
    (void)in_sizes; (void)n_in; (void)out_size;
    const float* x   = (const float*)d_in[0];
    const float* g1  = (const float*)d_in[1];
    const float* b1  = (const float*)d_in[2];
    const float* g2  = (const float*)d_in[3];
    const float* b2  = (const float*)d_in[4];
    const float* Wr  = (const float*)d_in[5];
    const float* br  = (const float*)d_in[6];
    const float* Wq  = (const float*)d_in[7];
    const float* bq  = (const float*)d_in[8];
    const float* Wk  = (const float*)d_in[9];
    const float* bk  = (const float*)d_in[10];
    const float* Wv  = (const float*)d_in[11];
    const float* bv  = (const float*)d_in[12];
    const float* Wo  = (const float*)d_in[13];
    const float* bo  = (const float*)d_in[14];
    const float* Wm  = (const float*)d_in[15];
    const float* bm  = (const float*)d_in[16];
    const float* W1  = (const float*)d_in[17];
    const float* bf1 = (const float*)d_in[18];
    const float* W2  = (const float*)d_in[19];
    const float* bf2 = (const float*)d_in[20];
    float* out = (float*)d_out;

    float *p_bkvm, *p_fp2;
    __half *p_nh, *p_qselh, *p_ctxh, *p_n2h, *p_th, *p_whuf;
    int* p_selidx;
    cudaGetSymbolAddress((void**)&p_nh,     g_nh);
    cudaGetSymbolAddress((void**)&p_bkvm,   g_bkvm);
    cudaGetSymbolAddress((void**)&p_qselh,  g_qselh);
    cudaGetSymbolAddress((void**)&p_ctxh,   g_ctxh);
    cudaGetSymbolAddress((void**)&p_n2h,    g_n2h);
    cudaGetSymbolAddress((void**)&p_th,     g_th);
    cudaGetSymbolAddress((void**)&p_whuf,   g_whuf);
    cudaGetSymbolAddress((void**)&p_selidx, g_selidx);
    cudaGetSymbolAddress((void**)&p_fp2,    g_fp2);

    __half* rKVM = p_whuf;                         // [2304][768]
    __half* rWq  = p_whuf + 3*(size_t)WSZ_;
    __half* rWo  = p_whuf + 4*(size_t)WSZ_;
    __half* rW1  = p_whuf + 5*(size_t)WSZ_;
    __half* rW2  = rW1 + (size_t)W1SZ_;

    // 0. fused weight prep (single launch)
    TP7 tp;
    tp.in[0]=Wk; tp.out[0]=rKVM + 0*(size_t)WSZ_; tp.K[0]=D_; tp.N[0]=D_;
    tp.in[1]=Wv; tp.out[1]=rKVM + 1*(size_t)WSZ_; tp.K[1]=D_; tp.N[1]=D_;
    tp.in[2]=Wm; tp.out[2]=rKVM + 2*(size_t)WSZ_; tp.K[2]=D_; tp.N[2]=D_;
    tp.in[3]=Wq; tp.out[3]=rWq;                   tp.K[3]=D_; tp.N[3]=D_;
    tp.in[4]=Wo; tp.out[4]=rWo;                   tp.K[4]=D_; tp.N[4]=D_;
    tp.in[5]=W1; tp.out[5]=rW1;                   tp.K[5]=D_; tp.N[5]=F_;
    tp.in[6]=W2; tp.out[6]=rW2;                   tp.K[6]=F_; tp.N[6]=D_;
    int total = 0;
    for (int s = 0; s < 7; s++) {
        tp.cum[s] = total;
        total += (tp.K[s]/64) * (tp.N[s]/32);
    }
    tp.cum[7] = total;
    transpose_all_kernel<<<total, dim3(32, 8)>>>(tp);
    bias_concat_kernel<<<9, 256>>>(bk, bv, bm);
    // 1. LN1 + router
    ln1_router_kernel<<<BL_, 256>>>(x, g1, b1, Wr, br);
    // 2. top-k (histogram select + rank counting)
    topk_kernel<<<B_, 1024>>>();
    // 3. pooling path (part + fused fin/Wm)
    pooled_part_kernel<<<dim3(16, B_), D_>>>();
    pooledwm_kernel<<<dim3(3, B_), 256>>>(Wm);
    // 4. fused K|V|mix projection (N=2304): K,V -> fp16, mix -> f32
    gemm_h<5,false><<<dim3(NKVM_/128, BL_/128), 128>>>(p_nh, nullptr, rKVM, p_bkvm, nullptr, nullptr, BL_, NKVM_, D_);
    // 5. Q for selected rows (gather, split-K=4) -> fin -> fp16
    gemm_h<4,true ><<<dim3(D_/128, (MSEL_+127)/128, QZ_), 128>>>(p_nh, p_selidx, rWq, nullptr, p_fp2, nullptr, MSEL_, D_, D_);
    qfin<<<(MSEL_*D_ + 255)/256, 256>>>(bq);
    // 6. flash attention (split-KV, 32-key chunks) + combine
    flash_attn<<<dim3(5, B_*H_, NSPL_), 128>>>();
    attn_combine<<<dim3(5, B_*H_), 256>>>();
    // Wo projection (split-K=4): partials consumed directly by merge_ln2
    gemm_h<4,false><<<dim3(D_/128, (MSEL_+127)/128, QZ_), 128>>>(p_ctxh, nullptr, rWo, nullptr, p_fp2, nullptr, MSEL_, D_, D_);
    // 7. merge (Wo fin fused) + residual + LN2
    merge_ln2_kernel<<<BL_, 256>>>(x, g2, b2, bo);
    // 8. FFN: FFN1 GELU -> fp16; FFN2 split-K=2 -> partials -> fin(out)
    gemm_h<1,false><<<dim3(F_/128, BL_/128), 128>>>(p_n2h, nullptr, rW1, bf1, nullptr, p_th, BL_, F_, D_);
    gemm_h<4,false><<<dim3(D_/128, BL_/128, 2), 128>>>(p_th, nullptr, rW2, nullptr, p_fp2, nullptr, BL_, D_, F_);
    ffn2_fin<<<(BL_*D_/4)/256, 256>>>(bf2, out);
}

// round 16
// speedup vs baseline: 1.0388x; 1.0038x over previous
#include <cuda_runtime.h>
#include <cuda_fp16.h>
#include <math.h>
#include <stdint.h>

// Problem constants
#define B_    4
#define L_    2048
#define D_    768
#define H_    12
#define DH_   64
#define F_    3072
#define KS_   307              // round(0.15 * 2048)
#define BL_   (B_*L_)          // 8192
#define MSEL_ (B_*KS_)         // 1228
#define NKVM_ 2304             // 3*D concat (K,V,M)
#define NSPL_ 8                // KV splits in flash attention
#define JSEG_ (L_/NSPL_)       // 256
#define QZ_   4                // split-K for Q/Wo GEMMs

#define WSZ_  589824           // 768*768
#define W1SZ_ 2359296          // 768*3072

// ---------------- scratch (static device globals; allocation-free) ----------
__device__ __align__(16) __half g_nh[BL_*(size_t)D_];   // fp16 LN1 output
__device__ float g_scores[BL_];
__device__ float g_ssum[B_];
__device__ int   g_selidx[MSEL_];
__device__ int   g_selpos[BL_];
__device__ float g_ppart[B_*16*D_];
__device__ float g_pooledWm[B_*D_];
__device__ __align__(16) __half g_khf[BL_*(size_t)D_];  // fp16 K
__device__ __align__(16) __half g_vhf[BL_*(size_t)D_];  // fp16 V
__device__ float g_mixb[BL_*(size_t)D_];                // fp32 mix base
__device__ float g_bkvm[NKVM_];
__device__ __align__(16) __half g_qselh[MSEL_*(size_t)D_];
__device__ float g_po[(size_t)B_*H_*NSPL_*320*64];   // attention partial O
__device__ float g_pm[B_*H_*NSPL_*320];
__device__ float g_pl[B_*H_*NSPL_*320];
__device__ __align__(16) __half g_ctxh[MSEL_*(size_t)D_];
__device__ float g_h[BL_*(size_t)D_];
__device__ __align__(16) __half g_n2h[BL_*(size_t)D_];
__device__ __align__(16) __half g_th[BL_*(size_t)F_];
__device__ float g_fp2[2*(size_t)BL_*D_];     // split-K partials (reused: Q, Wo, FFN2)
__device__ __align__(16) __half g_whuf[5*(size_t)WSZ_ + 2*(size_t)W1SZ_];  // fp16 [N][K] weights

// ---------------- small helpers ----------------
__device__ __forceinline__ uint32_t smem_u32(const void* p) {
    uint32_t a;
    asm("{ .reg .u64 t; cvta.to.shared.u64 t, %1; cvt.u32.u64 %0, t; }"
        : "=r"(a) : "l"(p));
    return a;
}
__device__ __forceinline__ void mma16n8k16h(float* c, const uint32_t* a, const uint32_t* b) {
    asm volatile(
        "mma.sync.aligned.m16n8k16.row.col.f32.f16.f16.f32 "
        "{%0,%1,%2,%3}, {%4,%5,%6,%7}, {%8,%9}, {%0,%1,%2,%3};"
        : "+f"(c[0]), "+f"(c[1]), "+f"(c[2]), "+f"(c[3])
        : "r"(a[0]), "r"(a[1]), "r"(a[2]), "r"(a[3]), "r"(b[0]), "r"(b[1]));
}
__device__ __forceinline__ void ldsm4(uint32_t* r, uint32_t addr) {
    asm volatile("ldmatrix.sync.aligned.m8n8.x4.shared.b16 {%0,%1,%2,%3}, [%4];"
        : "=r"(r[0]), "=r"(r[1]), "=r"(r[2]), "=r"(r[3]) : "r"(addr));
}
__device__ __forceinline__ void cpasync16(uint32_t dst, const void* src, unsigned sz) {
    asm volatile("cp.async.cg.shared.global [%0], [%1], 16, %2;"
        :: "r"(dst), "l"(src), "r"(sz));
}
__device__ __forceinline__ void cpcommit() { asm volatile("cp.async.commit_group;"); }
__device__ __forceinline__ void cpwait0()  { asm volatile("cp.async.wait_group 0;"); }
__device__ __forceinline__ void cpwait1()  { asm volatile("cp.async.wait_group 1;"); }

// ---------------- reductions ----------------
__device__ __forceinline__ float blockReduceSum(float v, float* sh) {
    __syncthreads();
    int lane = threadIdx.x & 31, w = threadIdx.x >> 5;
    #pragma unroll
    for (int o = 16; o > 0; o >>= 1) v += __shfl_xor_sync(0xffffffffu, v, o);
    if (lane == 0) sh[w] = v;
    __syncthreads();
    int nw = (blockDim.x + 31) >> 5;
    if (w == 0) {
        v = (lane < nw) ? sh[lane] : 0.f;
        #pragma unroll
        for (int o = 16; o > 0; o >>= 1) v += __shfl_xor_sync(0xffffffffu, v, o);
        if (lane == 0) sh[0] = v;
    }
    __syncthreads();
    return sh[0];
}

// ---------------- W prep: fused 7-way transpose [K][N] fp32 -> [N][K] fp16 --
struct TP7 {
    const float* in[7];
    __half* out[7];
    int K[7], N[7];
    int cum[8];
};
__global__ void transpose_all_kernel(TP7 p) {
    __shared__ float tile[64][33];
    int flat = blockIdx.x;
    int s = 0;
    #pragma unroll
    for (int i = 1; i < 7; i++) s += (flat >= p.cum[i]);
    int id = flat - p.cum[s];
    int K = p.K[s], N = p.N[s];
    int ntl = N >> 5;
    int k0 = (id / ntl) * 64, n0 = (id % ntl) * 32;
    const float* in = p.in[s];
    __half* out = p.out[s];
    int tx = threadIdx.x, ty = threadIdx.y;   // (32, 8)
    #pragma unroll
    for (int i = 0; i < 64; i += 8)
        tile[ty + i][tx] = in[(size_t)(k0 + ty + i) * N + n0 + tx];
    __syncthreads();
    #pragma unroll
    for (int i = 0; i < 32; i += 8) {
        int n = n0 + ty + i;
        __half2 v = __floats2half2_rn(tile[tx*2][ty + i], tile[tx*2 + 1][ty + i]);
        *reinterpret_cast<__half2*>(&out[(size_t)n * K + k0 + tx*2]) = v;
    }
}

__global__ void bias_concat_kernel(const float* __restrict__ bk, const float* __restrict__ bv,
                                   const float* __restrict__ bm) {
    int d = blockIdx.x * 256 + threadIdx.x;
    float v = (d < 768) ? bk[d] : ((d < 1536) ? bv[d - 768] : bm[d - 1536]);
    g_bkvm[d] = v;
}

// ---------------- K1: LN1 + router score ----------------
__global__ void ln1_router_kernel(const float* __restrict__ x, const float* __restrict__ g1,
                                  const float* __restrict__ b1, const float* __restrict__ Wr,
                                  const float* __restrict__ br) {
    int tok = blockIdx.x;
    int t = threadIdx.x;   // 256
    const float* xr = x + (size_t)tok * D_;
    __shared__ float sh[32];
    float v[3]; float s = 0.f, sq = 0.f;
    #pragma unroll
    for (int i = 0; i < 3; i++) { float u = xr[t + 256*i]; v[i] = u; s += u; sq += u*u; }
    s  = blockReduceSum(s,  sh);
    sq = blockReduceSum(sq, sh);
    float mean = s * (1.f/D_);
    float var  = sq * (1.f/D_) - mean*mean;
    float rstd = rsqrtf(var + 1e-5f);
    float dot = 0.f;
    #pragma unroll
    for (int i = 0; i < 3; i++) {
        int d = t + 256*i;
        float nv = (v[i] - mean) * rstd * g1[d] + b1[d];
        g_nh[(size_t)tok*D_ + d] = __float2half_rn(nv);
        dot += nv * Wr[d];
    }
    dot = blockReduceSum(dot, sh);
    if (t == 0) g_scores[tok] = 1.f / (1.f + expf(-(dot + br[0])));
}

// ---------------- K2: exact top-k via histogram select + rank counting -----
__global__ void topk_kernel() {
    int b = blockIdx.x, t = threadIdx.x;   // 1024 threads
    __shared__ int hist[2048];
    __shared__ unsigned long long cand[2048];
    __shared__ float sh[32];
    __shared__ int wsum[32];
    __shared__ int s_thr, s_below, s_ncand, s_ndir;
    hist[t] = 0; hist[t + 1024] = 0;
    if (t == 0) { s_ncand = 0; s_ndir = 0; }
    float s0 = g_scores[b*L_ + t];
    float s1 = g_scores[b*L_ + t + 1024];
    g_selpos[b*L_ + t] = -1;
    g_selpos[b*L_ + t + 1024] = -1;
    float tot = blockReduceSum(s0 + s1, sh);
    if (t == 0) g_ssum[b] = tot + 1e-6f;
    __syncthreads();
    unsigned u0 = __float_as_uint(s0) >> 21;
    unsigned u1 = __float_as_uint(s1) >> 21;
    atomicAdd(&hist[u0], 1);
    atomicAdd(&hist[u1], 1);
    __syncthreads();
    int h0 = hist[2*t], h1 = hist[2*t + 1];
    int pair = h0 + h1;
    int lane = t & 31, wrp = t >> 5;
    int v = pair;
    #pragma unroll
    for (int o = 1; o < 32; o <<= 1) {
        int u = __shfl_up_sync(0xffffffffu, v, o);
        if (lane >= o) v += u;
    }
    if (lane == 31) wsum[wrp] = v;
    __syncthreads();
    if (wrp == 0) {
        int u = wsum[lane];
        #pragma unroll
        for (int o = 1; o < 32; o <<= 1) {
            int z = __shfl_up_sync(0xffffffffu, u, o);
            if (lane >= o) u += z;
        }
        wsum[lane] = u;
    }
    __syncthreads();
    int incl_pair = v + (wrp ? wsum[wrp - 1] : 0);
    int excl = incl_pair - pair;
    int incl0 = excl + h0;
    if (incl0 >= KS_ && excl < KS_)       { s_thr = 2*t;     s_below = excl; }
    if (incl_pair >= KS_ && incl0 < KS_)  { s_thr = 2*t + 1; s_below = incl0; }
    __syncthreads();
    const int thr = s_thr, below = s_below;
    #pragma unroll
    for (int q = 0; q < 2; q++) {
        int tok = t + q*1024;
        float sv = q ? s1 : s0;
        unsigned uv = q ? u1 : u0;
        if ((int)uv < thr) {
            int slot = atomicAdd(&s_ndir, 1);
            g_selidx[b*KS_ + slot] = b*L_ + tok;
            g_selpos[b*L_ + tok] = b*KS_ + slot;
        } else if ((int)uv == thr) {
            int c = atomicAdd(&s_ncand, 1);
            cand[c] = ((unsigned long long)__float_as_uint(sv) << 32) | (unsigned)tok;
        }
    }
    __syncthreads();
    int ncand = s_ncand;
    int need = KS_ - below;
    for (int c = t; c < ncand; c += 1024) {
        unsigned long long key = cand[c];
        int rank = 0;
        for (int j = 0; j < ncand; j++) rank += (cand[j] < key);
        if (rank < need) {
            int tok = (int)(unsigned)(key & 0xffffffffULL);
            int slot = below + rank;
            g_selidx[b*KS_ + slot] = b*L_ + tok;
            g_selpos[b*L_ + tok] = b*KS_ + slot;
        }
    }
}

// ---------------- K3: coherence-weighted pooling (reads fp16 normed) -------
__global__ void pooled_part_kernel() {
    int b = blockIdx.y, ch = blockIdx.x;
    int d = threadIdx.x;
    float acc = 0.f;
    int l0 = ch * (L_/16);
    for (int l = l0; l < l0 + L_/16; l++)
        acc += g_scores[b*L_ + l] * __half2float(g_nh[((size_t)(b*L_ + l))*D_ + d]);
    g_ppart[(b*16 + ch)*D_ + d] = acc;
}
// fused: pooled_fin + pooled@Wm
__global__ void pooledwm_kernel(const float* __restrict__ Wm) {
    int b = blockIdx.y;
    __shared__ float pooled_s[D_];
    int tid = threadIdx.x;   // 256
    float sv = g_ssum[b];
    for (int d = tid; d < D_; d += 256) {
        float acc = 0.f;
        #pragma unroll
        for (int c = 0; c < 16; c++) acc += g_ppart[(b*16 + c)*D_ + d];
        pooled_s[d] = acc / sv;
    }
    __syncthreads();
    int n = blockIdx.x*256 + tid;
    float acc = 0.f;
    for (int d = 0; d < D_; d++) acc += pooled_s[d] * Wm[d*D_ + n];
    g_pooledWm[b*D_ + n] = acc;
}

// ---------------- fp16 GEMM body (device fn; smem passed in) ---------------
// OUT: 1 = GELU -> fp16 Ch; 4 = raw f32 partial (split-K, nz slices);
//      5 = KVM epilogue (K,V -> fp16, mix -> f32; + bias).
#define RS_  40                   // smem row stride in halves (80 B)
#define HSTG_ (128*RS_*2)         // bytes per stage per operand = 10240
template<int OUT, bool GATHER>
__device__ __forceinline__
void gemm_body(int bx, int by, int bz, int nz, __half* AsB, __half* BsB,
               const __half* __restrict__ A, const int* __restrict__ gidx,
               const __half* __restrict__ Bt, const float* __restrict__ bias,
               float* __restrict__ C, __half* __restrict__ Ch, int M, int N, int K) {
    const int tid = threadIdx.x, lane = tid & 31, wid = tid >> 5;
    const int wm = wid & 1, wn = wid >> 1;
    const int g = lane >> 2, t = lane & 3;
    const int m0 = by * 128, n0 = bx * 128;
    const int zk = K / nz;
    const int z0 = bz * zk;

    uint32_t sA = smem_u32(AsB);
    uint32_t sB = smem_u32(BsB);

    const __half* asrc[4]; unsigned asz[4]; uint32_t a_dst[4];
    const __half* bsrc[4]; uint32_t b_dst[4];
    #pragma unroll
    for (int j = 0; j < 4; j++) {
        int rl = j*32 + (tid >> 2);
        int ck = (tid & 3) * 8;
        int r = m0 + rl;
        bool v = r < M;
        int gr = v ? (GATHER ? gidx[r] : r) : 0;
        asrc[j]  = A + (size_t)gr*K + z0 + ck;
        asz[j]   = v ? 16u : 0u;
        a_dst[j] = sA + (uint32_t)(rl*RS_ + ck) * 2;
        bsrc[j]  = Bt + (size_t)(n0 + rl)*K + z0 + ck;
        b_dst[j] = sB + (uint32_t)(rl*RS_ + ck) * 2;
    }

    uint32_t a_ld = sA + (uint32_t)((wm*64 + (lane & 7) + ((lane >> 3) & 1)*8)*RS_
                                    + ((lane >> 4) & 1)*8) * 2;
    uint32_t b_ld = sB + (uint32_t)((wn*64 + (lane & 7) + ((lane >> 4) & 1)*8)*RS_
                                    + ((lane >> 3) & 1)*8) * 2;

    float acc[4][8][4] = {};
    const int ntiles = zk >> 5;

    auto issue = [&](int stage, int k0) {
        #pragma unroll
        for (int j = 0; j < 4; j++) cpasync16(a_dst[j] + stage*HSTG_, asrc[j] + k0, asz[j]);
        #pragma unroll
        for (int j = 0; j < 4; j++) cpasync16(b_dst[j] + stage*HSTG_, bsrc[j] + k0, 16u);
        cpcommit();
    };

    issue(0, 0);
    if (ntiles > 1) issue(1, 32);
    for (int it = 0; it < ntiles; it++) {
        int st = it % 3;
        if (it == ntiles - 1) cpwait0(); else cpwait1();
        __syncthreads();
        if (it + 2 < ntiles) issue((it + 2) % 3, (it + 2) << 5);
        #pragma unroll
        for (int kk = 0; kk < 32; kk += 16) {
            uint32_t a[4][4], bb[4][4];
            #pragma unroll
            for (int mt = 0; mt < 4; mt++)
                ldsm4(a[mt], a_ld + st*HSTG_ + mt*(16*RS_*2) + kk*2);
            #pragma unroll
            for (int np = 0; np < 4; np++)
                ldsm4(bb[np], b_ld + st*HSTG_ + np*(16*RS_*2) + kk*2);
            #pragma unroll
            for (int mt = 0; mt < 4; mt++)
                #pragma unroll
                for (int nt = 0; nt < 8; nt++) {
                    uint32_t bf[2] = { bb[nt >> 1][(nt & 1)*2], bb[nt >> 1][(nt & 1)*2 + 1] };
                    mma16n8k16h(acc[mt][nt], a[mt], bf);
                }
        }
        __syncthreads();
    }

    // ---- epilogue ----
    const size_t zout = (OUT == 4) ? (size_t)bz * M * N : 0;
    const int seg = n0 / 768;
    #pragma unroll
    for (int mt = 0; mt < 4; mt++) {
        #pragma unroll
        for (int nt = 0; nt < 8; nt++) {
            int n = n0 + wn*64 + nt*8 + t*2;
            float bi0 = (OUT == 4) ? 0.f : bias[n];
            float bi1 = (OUT == 4) ? 0.f : bias[n + 1];
            #pragma unroll
            for (int half = 0; half < 2; half++) {
                int m = m0 + wm*64 + mt*16 + g + half*8;
                if (m < M) {
                    float v0 = acc[mt][nt][half*2 + 0] + bi0;
                    float v1 = acc[mt][nt][half*2 + 1] + bi1;
                    size_t off = (size_t)m * N + n;
                    if (OUT == 1) {
                        v0 = 0.5f * v0 * (1.f + erff(v0 * 0.70710678118654752f));
                        v1 = 0.5f * v1 * (1.f + erff(v1 * 0.70710678118654752f));
                        *reinterpret_cast<__half2*>(Ch + off) = __floats2half2_rn(v0, v1);
                    } else if (OUT == 5) {
                        size_t off2 = (size_t)m * D_ + (n - seg*768);
                        if (seg == 0)
                            *reinterpret_cast<__half2*>(g_khf + off2) = __floats2half2_rn(v0, v1);
                        else if (seg == 1)
                            *reinterpret_cast<__half2*>(g_vhf + off2) = __floats2half2_rn(v0, v1);
                        else {
                            float2 o; o.x = v0; o.y = v1;
                            *(float2*)&g_mixb[off2] = o;
                        }
                    } else {
                        float2 o; o.x = v0; o.y = v1;
                        *(float2*)&C[zout + off] = o;
                    }
                }
            }
        }
    }
}

template<int OUT, bool GATHER>
__global__ __launch_bounds__(128)
void gemm_h(const __half* __restrict__ A, const int* __restrict__ gidx,
            const __half* __restrict__ Bt, const float* __restrict__ bias,
            float* __restrict__ C, __half* __restrict__ Ch, int M, int N, int K) {
    __shared__ __align__(128) __half As[3*128*RS_];
    __shared__ __align__(128) __half Bs[3*128*RS_];
    gemm_body<OUT, GATHER>(blockIdx.x, blockIdx.y, blockIdx.z, (int)gridDim.z,
                           As, Bs, A, gidx, Bt, bias, C, Ch, M, N, K);
}

// fused KVM (1152 blocks) + Q split-K (240 blocks): packs Q into KVM tail wave
#define KVMB_ (18*64)
__global__ __launch_bounds__(128)
void kvmq_kernel(const __half* __restrict__ nh, const int* __restrict__ selidx,
                 const __half* __restrict__ rKVM, const float* __restrict__ bkvm,
                 const __half* __restrict__ rWq, float* __restrict__ fp2) {
    __shared__ __align__(128) __half As[3*128*RS_];
    __shared__ __align__(128) __half Bs[3*128*RS_];
    int f = blockIdx.x;
    if (f < KVMB_) {
        gemm_body<5,false>(f % 18, f / 18, 0, 1, As, Bs,
                           nh, nullptr, rKVM, bkvm, nullptr, nullptr, BL_, NKVM_, D_);
    } else {
        int r = f - KVMB_;          // 0..239
        int bz = r / 60;            // 60 = 6 x 10 per z-slice
        int rr = r % 60;
        gemm_body<4,true>(rr % 6, rr / 6, bz, QZ_, As, Bs,
                          nh, selidx, rWq, nullptr, fp2, nullptr, MSEL_, D_, D_);
    }
}

// finish split-K=QZ_ Q partials -> fp16 qselh (+ bias)
__global__ __launch_bounds__(256) void qfin(const float* __restrict__ bq) {
    int i = blockIdx.x * 256 + threadIdx.x;
    if (i < MSEL_*D_) {
        float acc = 0.f;
        #pragma unroll
        for (int z = 0; z < QZ_; z++) acc += g_fp2[(size_t)z*MSEL_*D_ + i];
        g_qselh[i] = __float2half_rn(acc + bq[i % D_]);
    }
}

// FFN2 finish: out = part0 + part1 + bias + h
__global__ __launch_bounds__(256) void ffn2_fin(const float* __restrict__ bf2,
                                                float* __restrict__ out) {
    int i = blockIdx.x * 256 + threadIdx.x;
    const float4* p0 = (const float4*)g_fp2;
    const float4* p1 = (const float4*)(g_fp2 + (size_t)BL_*D_);
    const float4* ph = (const float4*)g_h;
    float4 a = p0[i], b = p1[i], hh = ph[i];
    float4 bi = ((const float4*)bf2)[i % (D_/4)];
    float4 o;
    o.x = a.x + b.x + hh.x + bi.x;
    o.y = a.y + b.y + hh.y + bi.y;
    o.z = a.z + b.z + hh.z + bi.z;
    o.w = a.w + b.w + hh.w + bi.w;
    ((float4*)out)[i] = o;
}

// ---------------- flash attention, split-KV, fp16 mma, 32-key chunks -------
#define QST_ 72
#define VST_ 40
__global__ __launch_bounds__(128) void flash_attn() {
    const int it = blockIdx.x, bh = blockIdx.y, sp = blockIdx.z;
    const int b = bh / H_, h = bh % H_;
    const int i0 = it * 64;
    __shared__ __align__(128) __half Qh[64][QST_];
    __shared__ __align__(128) __half Kh[32][QST_];
    __shared__ __align__(128) __half Vt[64][VST_];
    __shared__ __align__(128) __half Ph[4][16][VST_];
    const int tid = threadIdx.x, lane = tid & 31, w = tid >> 5;
    const int g = lane >> 2, t = lane & 3;

    #pragma unroll
    for (int q = 0; q < 4; q++) {
        int idx = q*128 + tid;
        int r = idx >> 3, c8 = (idx & 7) * 8;
        int i = i0 + r;
        uint4 v = make_uint4(0u, 0u, 0u, 0u);
        if (i < KS_) v = *(const uint4*)&g_qselh[((size_t)(b*KS_ + i))*D_ + h*DH_ + c8];
        *(uint4*)&Qh[r][c8] = v;
    }

    const uint32_t a_ldQ = smem_u32(&Qh[0][0])
        + (uint32_t)((w*16 + (lane & 7) + ((lane >> 3) & 1)*8)*QST_ + ((lane >> 4) & 1)*8) * 2;
    const uint32_t b_ldK = smem_u32(&Kh[0][0])
        + (uint32_t)(((lane & 7) + ((lane >> 4) & 1)*8)*QST_ + ((lane >> 3) & 1)*8) * 2;
    const uint32_t b_ldV = smem_u32(&Vt[0][0])
        + (uint32_t)(((lane & 7) + ((lane >> 4) & 1)*8)*VST_ + ((lane >> 3) & 1)*8) * 2;
    const uint32_t a_ldP = smem_u32(&Ph[w][0][0])
        + (uint32_t)(((lane & 7) + ((lane >> 3) & 1)*8)*VST_ + ((lane >> 4) & 1)*8) * 2;

    float accO[8][4] = {};
    float m0r = -1e30f, m1r = -1e30f, l0r = 0.f, l1r = 0.f;
    __syncthreads();

    for (int j0 = sp * JSEG_; j0 < (sp + 1) * JSEG_; j0 += 32) {
        #pragma unroll
        for (int q = 0; q < 2; q++) {
            int idx = q*128 + tid;
            int r = idx >> 3, c8 = (idx & 7) * 8;
            *(uint4*)&Kh[r][c8] =
                *(const uint4*)&g_khf[((size_t)(b*L_ + j0 + r))*D_ + h*DH_ + c8];
        }
        #pragma unroll
        for (int q = 0; q < 2; q++) {
            int idx = q*128 + tid;
            int r = idx & 31, c0 = (idx >> 5) * 8;
            uint4 vv = *(const uint4*)&g_vhf[((size_t)(b*L_ + j0 + r))*D_ + h*DH_ + c0];
            const __half* hp = reinterpret_cast<const __half*>(&vv);
            #pragma unroll
            for (int i = 0; i < 8; i++) Vt[c0 + i][r] = hp[i];
        }
        __syncthreads();

        float sacc[4][4] = {};
        #pragma unroll
        for (int ks = 0; ks < 4; ks++) {
            uint32_t a[4], bb[2][4];
            ldsm4(a, a_ldQ + ks*32);
            ldsm4(bb[0], b_ldK + ks*32);
            ldsm4(bb[1], b_ldK + 16*QST_*2 + ks*32);
            #pragma unroll
            for (int nt = 0; nt < 4; nt++) {
                uint32_t bf[2] = { bb[nt >> 1][(nt & 1)*2], bb[nt >> 1][(nt & 1)*2 + 1] };
                mma16n8k16h(sacc[nt], a, bf);
            }
        }
        float cm0 = -1e30f, cm1 = -1e30f;
        #pragma unroll
        for (int nt = 0; nt < 4; nt++) {
            sacc[nt][0] *= 0.125f; sacc[nt][1] *= 0.125f;
            sacc[nt][2] *= 0.125f; sacc[nt][3] *= 0.125f;
            cm0 = fmaxf(cm0, fmaxf(sacc[nt][0], sacc[nt][1]));
            cm1 = fmaxf(cm1, fmaxf(sacc[nt][2], sacc[nt][3]));
        }
        cm0 = fmaxf(cm0, __shfl_xor_sync(0xffffffffu, cm0, 1));
        cm0 = fmaxf(cm0, __shfl_xor_sync(0xffffffffu, cm0, 2));
        cm1 = fmaxf(cm1, __shfl_xor_sync(0xffffffffu, cm1, 1));
        cm1 = fmaxf(cm1, __shfl_xor_sync(0xffffffffu, cm1, 2));
        float mn0 = fmaxf(m0r, cm0), mn1 = fmaxf(m1r, cm1);
        float al0 = expf(m0r - mn0), al1 = expf(m1r - mn1);
        m0r = mn0; m1r = mn1;
        float s0 = 0.f, s1 = 0.f;
        #pragma unroll
        for (int nt = 0; nt < 4; nt++) {
            float p0 = expf(sacc[nt][0] - mn0);
            float p1 = expf(sacc[nt][1] - mn0);
            float p2 = expf(sacc[nt][2] - mn1);
            float p3 = expf(sacc[nt][3] - mn1);
            s0 += p0 + p1; s1 += p2 + p3;
            int c = nt*8 + t*2;
            *reinterpret_cast<__half2*>(&Ph[w][g][c])     = __floats2half2_rn(p0, p1);
            *reinterpret_cast<__half2*>(&Ph[w][g + 8][c]) = __floats2half2_rn(p2, p3);
        }
        s0 += __shfl_xor_sync(0xffffffffu, s0, 1);
        s0 += __shfl_xor_sync(0xffffffffu, s0, 2);
        s1 += __shfl_xor_sync(0xffffffffu, s1, 1);
        s1 += __shfl_xor_sync(0xffffffffu, s1, 2);
        l0r = l0r*al0 + s0; l1r = l1r*al1 + s1;
        #pragma unroll
        for (int nt = 0; nt < 8; nt++) {
            accO[nt][0] *= al0; accO[nt][1] *= al0;
            accO[nt][2] *= al1; accO[nt][3] *= al1;
        }
        __syncwarp();
        #pragma unroll
        for (int ks = 0; ks < 2; ks++) {
            uint32_t a[4];
            ldsm4(a, a_ldP + ks*32);
            uint32_t bb[4][4];
            #pragma unroll
            for (int np = 0; np < 4; np++)
                ldsm4(bb[np], b_ldV + np*(16*VST_*2) + ks*32);
            #pragma unroll
            for (int nt = 0; nt < 8; nt++) {
                uint32_t bf[2] = { bb[nt >> 1][(nt & 1)*2], bb[nt >> 1][(nt & 1)*2 + 1] };
                mma16n8k16h(accO[nt], a, bf);
            }
        }
        __syncthreads();
    }

    const size_t slot0 = (size_t)(bh*NSPL_ + sp)*320 + it*64 + w*16 + g;
    const size_t slot1 = slot0 + 8;
    if (t == 0) {
        g_pm[slot0] = m0r; g_pl[slot0] = l0r;
        g_pm[slot1] = m1r; g_pl[slot1] = l1r;
    }
    #pragma unroll
    for (int nt = 0; nt < 8; nt++) {
        int c = nt*8 + t*2;
        g_po[slot0*64 + c]     = accO[nt][0];
        g_po[slot0*64 + c + 1] = accO[nt][1];
        g_po[slot1*64 + c]     = accO[nt][2];
        g_po[slot1*64 + c + 1] = accO[nt][3];
    }
}

// combine split-KV partials -> g_ctxh (fp16, feeds Wo GEMM)
__global__ __launch_bounds__(256) void attn_combine() {
    const int it = blockIdx.x, bh = blockIdx.y;
    const int b = bh / H_, h = bh % H_;
    __shared__ float ws[64][NSPL_];
    __shared__ float linv[64];
    const int tid = threadIdx.x;
    if (tid < 64) {
        size_t base = (size_t)(bh*NSPL_)*320 + it*64 + tid;
        float mv[NSPL_]; float m = -1e30f;
        #pragma unroll
        for (int s = 0; s < NSPL_; s++) { mv[s] = g_pm[base + (size_t)s*320]; m = fmaxf(m, mv[s]); }
        float l = 0.f;
        #pragma unroll
        for (int s = 0; s < NSPL_; s++) {
            float wv = expf(mv[s] - m);
            ws[tid][s] = wv;
            l += g_pl[base + (size_t)s*320] * wv;
        }
        linv[tid] = 1.f / l;
    }
    __syncthreads();
    #pragma unroll
    for (int q = 0; q < 16; q++) {
        int idx = q*256 + tid;
        int r = idx >> 6, c = idx & 63;
        int i = it*64 + r;
        if (i < KS_) {
            size_t slot = (size_t)(bh*NSPL_)*320 + it*64 + r;
            float acc = 0.f;
            #pragma unroll
            for (int s = 0; s < NSPL_; s++)
                acc += g_po[(slot + (size_t)s*320)*64 + c] * ws[r][s];
            g_ctxh[((size_t)(b*KS_ + i))*D_ + h*DH_ + c] = __float2half_rn(acc * linv[r]);
        }
    }
}

// ---------------- merge paths (Wo split-K fin fused) + residual + LN2 ------
__global__ void merge_ln2_kernel(const float* __restrict__ x, const float* __restrict__ g2,
                                 const float* __restrict__ b2, const float* __restrict__ bo) {
    int tok = blockIdx.x;
    int b = tok >> 11;
    int t = threadIdx.x;
    int pos = g_selpos[tok];
    float sc = g_scores[tok];
    __shared__ float sh[32];
    float hv[3]; float s = 0.f, sq = 0.f;
    #pragma unroll
    for (int i = 0; i < 3; i++) {
        int d = t + 256*i;
        float mg;
        if (pos >= 0) {
            mg = bo[d];
            size_t base = (size_t)pos*D_ + d;
            #pragma unroll
            for (int z = 0; z < QZ_; z++) mg += g_fp2[(size_t)z*MSEL_*D_ + base];
        } else {
            mg = g_mixb[(size_t)tok*D_ + d] + sc * g_pooledWm[b*D_ + d];
        }
        float u = x[(size_t)tok*D_ + d] + mg;
        hv[i] = u;
        g_h[(size_t)tok*D_ + d] = u;
        s += u; sq += u*u;
    }
    s  = blockReduceSum(s,  sh);
    sq = blockReduceSum(sq, sh);
    float mean = s * (1.f/D_);
    float rstd = rsqrtf(sq*(1.f/D_) - mean*mean + 1e-5f);
    #pragma unroll
    for (int i = 0; i < 3; i++) {
        int d = t + 256*i;
        g_n2h[(size_t)tok*D_ + d] = __float2half_rn((hv[i] - mean) * rstd * g2[d] + b2[d]);
    }
}

// ---------------- host launch ----------------
extern "C" void kernel_launch(void* const* d_in, const int* in_sizes, int n_in,
                              void* d_out, int out_size) {
    (void)in_sizes; (void)n_in; (void)out_size;
    const float* x   = (const float*)d_in[0];
    const float* g1  = (const float*)d_in[1];
    const float* b1  = (const float*)d_in[2];
    const float* g2  = (const float*)d_in[3];
    const float* b2  = (const float*)d_in[4];
    const float* Wr  = (const float*)d_in[5];
    const float* br  = (const float*)d_in[6];
    const float* Wq  = (const float*)d_in[7];
    const float* bq  = (const float*)d_in[8];
    const float* Wk  = (const float*)d_in[9];
    const float* bk  = (const float*)d_in[10];
    const float* Wv  = (const float*)d_in[11];
    const float* bv  = (const float*)d_in[12];
    const float* Wo  = (const float*)d_in[13];
    const float* bo  = (const float*)d_in[14];
    const float* Wm  = (const float*)d_in[15];
    const float* bm  = (const float*)d_in[16];
    const float* W1  = (const float*)d_in[17];
    const float* bf1 = (const float*)d_in[18];
    const float* W2  = (const float*)d_in[19];
    const float* bf2 = (const float*)d_in[20];
    float* out = (float*)d_out;

    float *p_bkvm, *p_fp2;
    __half *p_nh, *p_qselh, *p_ctxh, *p_n2h, *p_th, *p_whuf;
    int* p_selidx;
    cudaGetSymbolAddress((void**)&p_nh,     g_nh);
    cudaGetSymbolAddress((void**)&p_bkvm,   g_bkvm);
    cudaGetSymbolAddress((void**)&p_qselh,  g_qselh);
    cudaGetSymbolAddress((void**)&p_ctxh,   g_ctxh);
    cudaGetSymbolAddress((void**)&p_n2h,    g_n2h);
    cudaGetSymbolAddress((void**)&p_th,     g_th);
    cudaGetSymbolAddress((void**)&p_whuf,   g_whuf);
    cudaGetSymbolAddress((void**)&p_selidx, g_selidx);
    cudaGetSymbolAddress((void**)&p_fp2,    g_fp2);

    __half* rKVM = p_whuf;                         // [2304][768]
    __half* rWq  = p_whuf + 3*(size_t)WSZ_;
    __half* rWo  = p_whuf + 4*(size_t)WSZ_;
    __half* rW1  = p_whuf + 5*(size_t)WSZ_;
    __half* rW2  = rW1 + (size_t)W1SZ_;

    // 0. fused weight prep (single launch)
    TP7 tp;
    tp.in[0]=Wk; tp.out[0]=rKVM + 0*(size_t)WSZ_; tp.K[0]=D_; tp.N[0]=D_;
    tp.in[1]=Wv; tp.out[1]=rKVM + 1*(size_t)WSZ_; tp.K[1]=D_; tp.N[1]=D_;
    tp.in[2]=Wm; tp.out[2]=rKVM + 2*(size_t)WSZ_; tp.K[2]=D_; tp.N[2]=D_;
    tp.in[3]=Wq; tp.out[3]=rWq;                   tp.K[3]=D_; tp.N[3]=D_;
    tp.in[4]=Wo; tp.out[4]=rWo;                   tp.K[4]=D_; tp.N[4]=D_;
    tp.in[5]=W1; tp.out[5]=rW1;                   tp.K[5]=D_; tp.N[5]=F_;
    tp.in[6]=W2; tp.out[6]=rW2;                   tp.K[6]=F_; tp.N[6]=D_;
    int total = 0;
    for (int s = 0; s < 7; s++) {
        tp.cum[s] = total;
        total += (tp.K[s]/64) * (tp.N[s]/32);
    }
    tp.cum[7] = total;
    transpose_all_kernel<<<total, dim3(32, 8)>>>(tp);
    bias_concat_kernel<<<9, 256>>>(bk, bv, bm);
    // 1. LN1 + router
    ln1_router_kernel<<<BL_, 256>>>(x, g1, b1, Wr, br);
    // 2. top-k (histogram select + rank counting)
    topk_kernel<<<B_, 1024>>>();
    // 3. pooling path (part + fused fin/Wm)
    pooled_part_kernel<<<dim3(16, B_), D_>>>();
    pooledwm_kernel<<<dim3(3, B_), 256>>>(Wm);
    // 4+5. fused: K|V|mix projection + Q gather split-K (one launch, tail-packed)
    kvmq_kernel<<<KVMB_ + 60*QZ_, 128>>>(p_nh, p_selidx, rKVM, p_bkvm, rWq, p_fp2);
    qfin<<<(MSEL_*D_ + 255)/256, 256>>>(bq);
    // 6. flash attention (split-KV=8, 32-key chunks) + combine
    flash_attn<<<dim3(5, B_*H_, NSPL_), 128>>>();
    attn_combine<<<dim3(5, B_*H_), 256>>>();
    // Wo projection (split-K=4): partials consumed directly by merge_ln2
    gemm_h<4,false><<<dim3(D_/128, (MSEL_+127)/128, QZ_), 128>>>(p_ctxh, nullptr, rWo, nullptr, p_fp2, nullptr, MSEL_, D_, D_);
    // 7. merge (Wo fin fused) + residual + LN2
    merge_ln2_kernel<<<BL_, 256>>>(x, g2, b2, bo);
    // 8. FFN: FFN1 GELU -> fp16; FFN2 split-K=2 -> partials -> fin(out)
    gemm_h<1,false><<<dim3(F_/128, BL_/128), 128>>>(p_n2h, nullptr, rW1, bf1, nullptr, p_th, BL_, F_, D_);
    gemm_h<4,false><<<dim3(D_/128, BL_/128, 2), 128>>>(p_th, nullptr, rW2, nullptr, p_fp2, nullptr, BL_, D_, F_);
    ffn2_fin<<<(BL_*D_/4)/256, 256>>>(bf2, out);
}

// round 17
// speedup vs baseline: 1.0905x; 1.0498x over previous
#include <cuda_runtime.h>
#include <cuda_fp16.h>
#include <math.h>
#include <stdint.h>

// Problem constants
#define B_    4
#define L_    2048
#define D_    768
#define H_    12
#define DH_   64
#define F_    3072
#define KS_   307              // round(0.15 * 2048)
#define BL_   (B_*L_)          // 8192
#define MSEL_ (B_*KS_)         // 1228
#define NKVM_ 2304             // 3*D concat (K,V,M)
#define NSPL_ 8                // KV splits in flash attention
#define JSEG_ (L_/NSPL_)       // 256
#define QZ_   4                // split-K for Q/Wo GEMMs

#define WSZ_  589824           // 768*768
#define W1SZ_ 2359296          // 768*3072

// ---------------- scratch (static device globals; allocation-free) ----------
__device__ __align__(16) __half g_nh[BL_*(size_t)D_];   // fp16 LN1 output
__device__ float g_scores[BL_];
__device__ float g_ssum[B_];
__device__ int   g_selidx[MSEL_];
__device__ int   g_selpos[BL_];
__device__ float g_ppart[B_*16*D_];
__device__ float g_pooledWm[B_*D_];
__device__ __align__(16) __half g_khf[BL_*(size_t)D_];  // fp16 K
__device__ __align__(16) __half g_vhf[BL_*(size_t)D_];  // fp16 V
__device__ float g_mixb[BL_*(size_t)D_];                // fp32 mix base
__device__ float g_bkvm[NKVM_];
__device__ __align__(16) __half g_qselh[MSEL_*(size_t)D_];
__device__ float g_po[(size_t)B_*H_*NSPL_*320*64];   // attention partial O
__device__ float g_pm[B_*H_*NSPL_*320];
__device__ float g_pl[B_*H_*NSPL_*320];
__device__ __align__(16) __half g_ctxh[MSEL_*(size_t)D_];
__device__ float g_h[BL_*(size_t)D_];
__device__ __align__(16) __half g_n2h[BL_*(size_t)D_];
__device__ __align__(16) __half g_th[BL_*(size_t)F_];
__device__ float g_fp2[2*(size_t)BL_*D_];     // split-K partials (reused: Q, Wo, FFN2)
__device__ __align__(16) __half g_whuf[5*(size_t)WSZ_ + 2*(size_t)W1SZ_];  // fp16 [N][K] weights

// ---------------- small helpers ----------------
__device__ __forceinline__ uint32_t smem_u32(const void* p) {
    uint32_t a;
    asm("{ .reg .u64 t; cvta.to.shared.u64 t, %1; cvt.u32.u64 %0, t; }"
        : "=r"(a) : "l"(p));
    return a;
}
__device__ __forceinline__ void mma16n8k16h(float* c, const uint32_t* a, const uint32_t* b) {
    asm volatile(
        "mma.sync.aligned.m16n8k16.row.col.f32.f16.f16.f32 "
        "{%0,%1,%2,%3}, {%4,%5,%6,%7}, {%8,%9}, {%0,%1,%2,%3};"
        : "+f"(c[0]), "+f"(c[1]), "+f"(c[2]), "+f"(c[3])
        : "r"(a[0]), "r"(a[1]), "r"(a[2]), "r"(a[3]), "r"(b[0]), "r"(b[1]));
}
__device__ __forceinline__ void ldsm4(uint32_t* r, uint32_t addr) {
    asm volatile("ldmatrix.sync.aligned.m8n8.x4.shared.b16 {%0,%1,%2,%3}, [%4];"
        : "=r"(r[0]), "=r"(r[1]), "=r"(r[2]), "=r"(r[3]) : "r"(addr));
}
__device__ __forceinline__ void cpasync16(uint32_t dst, const void* src, unsigned sz) {
    asm volatile("cp.async.cg.shared.global [%0], [%1], 16, %2;"
        :: "r"(dst), "l"(src), "r"(sz));
}
__device__ __forceinline__ void cpcommit() { asm volatile("cp.async.commit_group;"); }
__device__ __forceinline__ void cpwait0()  { asm volatile("cp.async.wait_group 0;"); }
__device__ __forceinline__ void cpwait1()  { asm volatile("cp.async.wait_group 1;"); }

// ---------------- reductions ----------------
__device__ __forceinline__ float blockReduceSum(float v, float* sh) {
    __syncthreads();
    int lane = threadIdx.x & 31, w = threadIdx.x >> 5;
    #pragma unroll
    for (int o = 16; o > 0; o >>= 1) v += __shfl_xor_sync(0xffffffffu, v, o);
    if (lane == 0) sh[w] = v;
    __syncthreads();
    int nw = (blockDim.x + 31) >> 5;
    if (w == 0) {
        v = (lane < nw) ? sh[lane] : 0.f;
        #pragma unroll
        for (int o = 16; o > 0; o >>= 1) v += __shfl_xor_sync(0xffffffffu, v, o);
        if (lane == 0) sh[0] = v;
    }
    __syncthreads();
    return sh[0];
}

// ---------------- fused prologue: 7-way transpose + bias concat + LN1 ------
struct TP7 {
    const float* in[7];
    __half* out[7];
    int K[7], N[7];
    int cum[8];
};
#define TPB_ 3744
__global__ void prologue_kernel(TP7 p,
                                const float* __restrict__ bk, const float* __restrict__ bv,
                                const float* __restrict__ bm,
                                const float* __restrict__ x, const float* __restrict__ g1,
                                const float* __restrict__ b1, const float* __restrict__ Wr,
                                const float* __restrict__ br) {
    __shared__ float tile[64][33];
    __shared__ float sh[32];
    int flat = blockIdx.x;
    int tid = threadIdx.x;   // 256
    if (flat < TPB_) {
        // ---- weight transpose [K][N] fp32 -> [N][K] fp16 ----
        int s = 0;
        #pragma unroll
        for (int i = 1; i < 7; i++) s += (flat >= p.cum[i]);
        int id = flat - p.cum[s];
        int K = p.K[s], N = p.N[s];
        int ntl = N >> 5;
        int k0 = (id / ntl) * 64, n0 = (id % ntl) * 32;
        const float* in = p.in[s];
        __half* out = p.out[s];
        int tx = tid & 31, ty = tid >> 5;   // (32, 8)
        #pragma unroll
        for (int i = 0; i < 64; i += 8)
            tile[ty + i][tx] = in[(size_t)(k0 + ty + i) * N + n0 + tx];
        __syncthreads();
        #pragma unroll
        for (int i = 0; i < 32; i += 8) {
            int n = n0 + ty + i;
            __half2 v = __floats2half2_rn(tile[tx*2][ty + i], tile[tx*2 + 1][ty + i]);
            *reinterpret_cast<__half2*>(&out[(size_t)n * K + k0 + tx*2]) = v;
        }
    } else if (flat < TPB_ + 9) {
        // ---- bias concat ----
        int d = (flat - TPB_) * 256 + tid;
        float v = (d < 768) ? bk[d] : ((d < 1536) ? bv[d - 768] : bm[d - 1536]);
        g_bkvm[d] = v;
    } else {
        // ---- LN1 + router score ----
        int tok = flat - (TPB_ + 9);
        const float* xr = x + (size_t)tok * D_;
        float v[3]; float s = 0.f, sq = 0.f;
        #pragma unroll
        for (int i = 0; i < 3; i++) { float u = xr[tid + 256*i]; v[i] = u; s += u; sq += u*u; }
        s  = blockReduceSum(s,  sh);
        sq = blockReduceSum(sq, sh);
        float mean = s * (1.f/D_);
        float var  = sq * (1.f/D_) - mean*mean;
        float rstd = rsqrtf(var + 1e-5f);
        float dot = 0.f;
        #pragma unroll
        for (int i = 0; i < 3; i++) {
            int d = tid + 256*i;
            float nv = (v[i] - mean) * rstd * g1[d] + b1[d];
            g_nh[(size_t)tok*D_ + d] = __float2half_rn(nv);
            dot += nv * Wr[d];
        }
        dot = blockReduceSum(dot, sh);
        if (tid == 0) g_scores[tok] = 1.f / (1.f + expf(-(dot + br[0])));
    }
}

// ---------------- fused: top-k (blocks 0..3) + pooled_part (blocks 4..67) --
__global__ void topkpool_kernel() {
    __shared__ int hist[2048];
    __shared__ unsigned long long cand[2048];
    __shared__ float sh[32];
    __shared__ int wsum[32];
    __shared__ int s_thr, s_below, s_ncand, s_ndir;
    int f = blockIdx.x;
    int t = threadIdx.x;   // 1024
    if (f >= B_) {
        // ---- pooled_part: b = (f-4)/16, ch = (f-4)%16, d = t (<768) ----
        int idx = f - B_;
        int b = idx >> 4, ch = idx & 15;
        if (t < D_) {
            float acc = 0.f;
            int l0 = ch * (L_/16);
            for (int l = l0; l < l0 + L_/16; l++)
                acc += g_scores[b*L_ + l] * __half2float(g_nh[((size_t)(b*L_ + l))*D_ + t]);
            g_ppart[(b*16 + ch)*D_ + t] = acc;
        }
        return;
    }
    int b = f;
    hist[t] = 0; hist[t + 1024] = 0;
    if (t == 0) { s_ncand = 0; s_ndir = 0; }
    float s0 = g_scores[b*L_ + t];
    float s1 = g_scores[b*L_ + t + 1024];
    g_selpos[b*L_ + t] = -1;
    g_selpos[b*L_ + t + 1024] = -1;
    float tot = blockReduceSum(s0 + s1, sh);
    if (t == 0) g_ssum[b] = tot + 1e-6f;
    __syncthreads();
    unsigned u0 = __float_as_uint(s0) >> 21;
    unsigned u1 = __float_as_uint(s1) >> 21;
    atomicAdd(&hist[u0], 1);
    atomicAdd(&hist[u1], 1);
    __syncthreads();
    int h0 = hist[2*t], h1 = hist[2*t + 1];
    int pair = h0 + h1;
    int lane = t & 31, wrp = t >> 5;
    int v = pair;
    #pragma unroll
    for (int o = 1; o < 32; o <<= 1) {
        int u = __shfl_up_sync(0xffffffffu, v, o);
        if (lane >= o) v += u;
    }
    if (lane == 31) wsum[wrp] = v;
    __syncthreads();
    if (wrp == 0) {
        int u = wsum[lane];
        #pragma unroll
        for (int o = 1; o < 32; o <<= 1) {
            int z = __shfl_up_sync(0xffffffffu, u, o);
            if (lane >= o) u += z;
        }
        wsum[lane] = u;
    }
    __syncthreads();
    int incl_pair = v + (wrp ? wsum[wrp - 1] : 0);
    int excl = incl_pair - pair;
    int incl0 = excl + h0;
    if (incl0 >= KS_ && excl < KS_)       { s_thr = 2*t;     s_below = excl; }
    if (incl_pair >= KS_ && incl0 < KS_)  { s_thr = 2*t + 1; s_below = incl0; }
    __syncthreads();
    const int thr = s_thr, below = s_below;
    #pragma unroll
    for (int q = 0; q < 2; q++) {
        int tok = t + q*1024;
        float sv = q ? s1 : s0;
        unsigned uv = q ? u1 : u0;
        if ((int)uv < thr) {
            int slot = atomicAdd(&s_ndir, 1);
            g_selidx[b*KS_ + slot] = b*L_ + tok;
            g_selpos[b*L_ + tok] = b*KS_ + slot;
        } else if ((int)uv == thr) {
            int c = atomicAdd(&s_ncand, 1);
            cand[c] = ((unsigned long long)__float_as_uint(sv) << 32) | (unsigned)tok;
        }
    }
    __syncthreads();
    int ncand = s_ncand;
    int need = KS_ - below;
    for (int c = t; c < ncand; c += 1024) {
        unsigned long long key = cand[c];
        int rank = 0;
        for (int j = 0; j < ncand; j++) rank += (cand[j] < key);
        if (rank < need) {
            int tok = (int)(unsigned)(key & 0xffffffffULL);
            int slot = below + rank;
            g_selidx[b*KS_ + slot] = b*L_ + tok;
            g_selpos[b*L_ + tok] = b*KS_ + slot;
        }
    }
}

// ---------------- fp16 GEMM body (device fn; smem passed in) ---------------
// OUT: 1 = GELU -> fp16 Ch; 4 = raw f32 partial (split-K, nz slices);
//      5 = KVM epilogue (K,V -> fp16, mix -> f32; + bias).
#define RS_  40                   // smem row stride in halves (80 B)
#define HSTG_ (128*RS_*2)         // bytes per stage per operand = 10240
template<int OUT, bool GATHER>
__device__ __forceinline__
void gemm_body(int bx, int by, int bz, int nz, __half* AsB, __half* BsB,
               const __half* __restrict__ A, const int* __restrict__ gidx,
               const __half* __restrict__ Bt, const float* __restrict__ bias,
               float* __restrict__ C, __half* __restrict__ Ch, int M, int N, int K) {
    const int tid = threadIdx.x, lane = tid & 31, wid = tid >> 5;
    const int wm = wid & 1, wn = wid >> 1;
    const int g = lane >> 2, t = lane & 3;
    const int m0 = by * 128, n0 = bx * 128;
    const int zk = K / nz;
    const int z0 = bz * zk;

    uint32_t sA = smem_u32(AsB);
    uint32_t sB = smem_u32(BsB);

    const __half* asrc[4]; unsigned asz[4]; uint32_t a_dst[4];
    const __half* bsrc[4]; uint32_t b_dst[4];
    #pragma unroll
    for (int j = 0; j < 4; j++) {
        int rl = j*32 + (tid >> 2);
        int ck = (tid & 3) * 8;
        int r = m0 + rl;
        bool v = r < M;
        int gr = v ? (GATHER ? gidx[r] : r) : 0;
        asrc[j]  = A + (size_t)gr*K + z0 + ck;
        asz[j]   = v ? 16u : 0u;
        a_dst[j] = sA + (uint32_t)(rl*RS_ + ck) * 2;
        bsrc[j]  = Bt + (size_t)(n0 + rl)*K + z0 + ck;
        b_dst[j] = sB + (uint32_t)(rl*RS_ + ck) * 2;
    }

    uint32_t a_ld = sA + (uint32_t)((wm*64 + (lane & 7) + ((lane >> 3) & 1)*8)*RS_
                                    + ((lane >> 4) & 1)*8) * 2;
    uint32_t b_ld = sB + (uint32_t)((wn*64 + (lane & 7) + ((lane >> 4) & 1)*8)*RS_
                                    + ((lane >> 3) & 1)*8) * 2;

    float acc[4][8][4] = {};
    const int ntiles = zk >> 5;

    auto issue = [&](int stage, int k0) {
        #pragma unroll
        for (int j = 0; j < 4; j++) cpasync16(a_dst[j] + stage*HSTG_, asrc[j] + k0, asz[j]);
        #pragma unroll
        for (int j = 0; j < 4; j++) cpasync16(b_dst[j] + stage*HSTG_, bsrc[j] + k0, 16u);
        cpcommit();
    };

    issue(0, 0);
    if (ntiles > 1) issue(1, 32);
    for (int it = 0; it < ntiles; it++) {
        int st = it % 3;
        if (it == ntiles - 1) cpwait0(); else cpwait1();
        __syncthreads();
        if (it + 2 < ntiles) issue((it + 2) % 3, (it + 2) << 5);
        #pragma unroll
        for (int kk = 0; kk < 32; kk += 16) {
            uint32_t a[4][4], bb[4][4];
            #pragma unroll
            for (int mt = 0; mt < 4; mt++)
                ldsm4(a[mt], a_ld + st*HSTG_ + mt*(16*RS_*2) + kk*2);
            #pragma unroll
            for (int np = 0; np < 4; np++)
                ldsm4(bb[np], b_ld + st*HSTG_ + np*(16*RS_*2) + kk*2);
            #pragma unroll
            for (int mt = 0; mt < 4; mt++)
                #pragma unroll
                for (int nt = 0; nt < 8; nt++) {
                    uint32_t bf[2] = { bb[nt >> 1][(nt & 1)*2], bb[nt >> 1][(nt & 1)*2 + 1] };
                    mma16n8k16h(acc[mt][nt], a[mt], bf);
                }
        }
        __syncthreads();
    }

    // ---- epilogue ----
    const size_t zout = (OUT == 4) ? (size_t)bz * M * N : 0;
    const int seg = n0 / 768;
    #pragma unroll
    for (int mt = 0; mt < 4; mt++) {
        #pragma unroll
        for (int nt = 0; nt < 8; nt++) {
            int n = n0 + wn*64 + nt*8 + t*2;
            float bi0 = (OUT == 4) ? 0.f : bias[n];
            float bi1 = (OUT == 4) ? 0.f : bias[n + 1];
            #pragma unroll
            for (int half = 0; half < 2; half++) {
                int m = m0 + wm*64 + mt*16 + g + half*8;
                if (m < M) {
                    float v0 = acc[mt][nt][half*2 + 0] + bi0;
                    float v1 = acc[mt][nt][half*2 + 1] + bi1;
                    size_t off = (size_t)m * N + n;
                    if (OUT == 1) {
                        v0 = 0.5f * v0 * (1.f + erff(v0 * 0.70710678118654752f));
                        v1 = 0.5f * v1 * (1.f + erff(v1 * 0.70710678118654752f));
                        *reinterpret_cast<__half2*>(Ch + off) = __floats2half2_rn(v0, v1);
                    } else if (OUT == 5) {
                        size_t off2 = (size_t)m * D_ + (n - seg*768);
                        if (seg == 0)
                            *reinterpret_cast<__half2*>(g_khf + off2) = __floats2half2_rn(v0, v1);
                        else if (seg == 1)
                            *reinterpret_cast<__half2*>(g_vhf + off2) = __floats2half2_rn(v0, v1);
                        else {
                            float2 o; o.x = v0; o.y = v1;
                            *(float2*)&g_mixb[off2] = o;
                        }
                    } else {
                        float2 o; o.x = v0; o.y = v1;
                        *(float2*)&C[zout + off] = o;
                    }
                }
            }
        }
    }
}

template<int OUT, bool GATHER>
__global__ __launch_bounds__(128)
void gemm_h(const __half* __restrict__ A, const int* __restrict__ gidx,
            const __half* __restrict__ Bt, const float* __restrict__ bias,
            float* __restrict__ C, __half* __restrict__ Ch, int M, int N, int K) {
    __shared__ __align__(128) __half As[3*128*RS_];
    __shared__ __align__(128) __half Bs[3*128*RS_];
    gemm_body<OUT, GATHER>(blockIdx.x, blockIdx.y, blockIdx.z, (int)gridDim.z,
                           As, Bs, A, gidx, Bt, bias, C, Ch, M, N, K);
}

// fused KVM (1152) + Q split-K (240) + pooledwm (24) in one launch
#define KVMB_ (18*64)
__global__ __launch_bounds__(128)
void kvmq_kernel(const __half* __restrict__ nh, const int* __restrict__ selidx,
                 const __half* __restrict__ rKVM, const float* __restrict__ bkvm,
                 const __half* __restrict__ rWq, float* __restrict__ fp2,
                 const float* __restrict__ Wm) {
    __shared__ __align__(128) __half As[3*128*RS_];
    __shared__ __align__(128) __half Bs[3*128*RS_];
    int f = blockIdx.x;
    if (f < KVMB_) {
        gemm_body<5,false>(f % 18, f / 18, 0, 1, As, Bs,
                           nh, nullptr, rKVM, bkvm, nullptr, nullptr, BL_, NKVM_, D_);
    } else if (f < KVMB_ + 60*QZ_) {
        int r = f - KVMB_;          // 0..239
        int bz = r / 60;
        int rr = r % 60;
        gemm_body<4,true>(rr % 6, rr / 6, bz, QZ_, As, Bs,
                          nh, selidx, rWq, nullptr, fp2, nullptr, MSEL_, D_, D_);
    } else {
        // pooled fin + pooled@Wm: 24 blocks (b = idx/6, nb = idx%6), 128 thr
        int idx = f - (KVMB_ + 60*QZ_);
        int b = idx / 6, nb = idx % 6;
        float* ps = reinterpret_cast<float*>(As);   // 768 floats scratch
        int tid = threadIdx.x;
        float sv = g_ssum[b];
        for (int d = tid; d < D_; d += 128) {
            float acc = 0.f;
            #pragma unroll
            for (int c = 0; c < 16; c++) acc += g_ppart[(b*16 + c)*D_ + d];
            ps[d] = acc / sv;
        }
        __syncthreads();
        int n = nb*128 + tid;
        float acc = 0.f;
        for (int d = 0; d < D_; d++) acc += ps[d] * Wm[d*D_ + n];
        g_pooledWm[b*D_ + n] = acc;
    }
}

// finish split-K=QZ_ Q partials -> fp16 qselh (+ bias)
__global__ __launch_bounds__(256) void qfin(const float* __restrict__ bq) {
    int i = blockIdx.x * 256 + threadIdx.x;
    if (i < MSEL_*D_) {
        float acc = 0.f;
        #pragma unroll
        for (int z = 0; z < QZ_; z++) acc += g_fp2[(size_t)z*MSEL_*D_ + i];
        g_qselh[i] = __float2half_rn(acc + bq[i % D_]);
    }
}

// FFN2 finish: out = part0 + part1 + bias + h
__global__ __launch_bounds__(256) void ffn2_fin(const float* __restrict__ bf2,
                                                float* __restrict__ out) {
    int i = blockIdx.x * 256 + threadIdx.x;
    const float4* p0 = (const float4*)g_fp2;
    const float4* p1 = (const float4*)(g_fp2 + (size_t)BL_*D_);
    const float4* ph = (const float4*)g_h;
    float4 a = p0[i], b = p1[i], hh = ph[i];
    float4 bi = ((const float4*)bf2)[i % (D_/4)];
    float4 o;
    o.x = a.x + b.x + hh.x + bi.x;
    o.y = a.y + b.y + hh.y + bi.y;
    o.z = a.z + b.z + hh.z + bi.z;
    o.w = a.w + b.w + hh.w + bi.w;
    ((float4*)out)[i] = o;
}

// ---------------- flash attention, split-KV, fp16 mma, 32-key chunks -------
#define QST_ 72
#define VST_ 40
__global__ __launch_bounds__(128) void flash_attn() {
    const int it = blockIdx.x, bh = blockIdx.y, sp = blockIdx.z;
    const int b = bh / H_, h = bh % H_;
    const int i0 = it * 64;
    __shared__ __align__(128) __half Qh[64][QST_];
    __shared__ __align__(128) __half Kh[32][QST_];
    __shared__ __align__(128) __half Vt[64][VST_];
    __shared__ __align__(128) __half Ph[4][16][VST_];
    const int tid = threadIdx.x, lane = tid & 31, w = tid >> 5;
    const int g = lane >> 2, t = lane & 3;

    #pragma unroll
    for (int q = 0; q < 4; q++) {
        int idx = q*128 + tid;
        int r = idx >> 3, c8 = (idx & 7) * 8;
        int i = i0 + r;
        uint4 v = make_uint4(0u, 0u, 0u, 0u);
        if (i < KS_) v = *(const uint4*)&g_qselh[((size_t)(b*KS_ + i))*D_ + h*DH_ + c8];
        *(uint4*)&Qh[r][c8] = v;
    }

    const uint32_t a_ldQ = smem_u32(&Qh[0][0])
        + (uint32_t)((w*16 + (lane & 7) + ((lane >> 3) & 1)*8)*QST_ + ((lane >> 4) & 1)*8) * 2;
    const uint32_t b_ldK = smem_u32(&Kh[0][0])
        + (uint32_t)(((lane & 7) + ((lane >> 4) & 1)*8)*QST_ + ((lane >> 3) & 1)*8) * 2;
    const uint32_t b_ldV = smem_u32(&Vt[0][0])
        + (uint32_t)(((lane & 7) + ((lane >> 4) & 1)*8)*VST_ + ((lane >> 3) & 1)*8) * 2;
    const uint32_t a_ldP = smem_u32(&Ph[w][0][0])
        + (uint32_t)(((lane & 7) + ((lane >> 3) & 1)*8)*VST_ + ((lane >> 4) & 1)*8) * 2;

    float accO[8][4] = {};
    float m0r = -1e30f, m1r = -1e30f, l0r = 0.f, l1r = 0.f;
    __syncthreads();

    for (int j0 = sp * JSEG_; j0 < (sp + 1) * JSEG_; j0 += 32) {
        #pragma unroll
        for (int q = 0; q < 2; q++) {
            int idx = q*128 + tid;
            int r = idx >> 3, c8 = (idx & 7) * 8;
            *(uint4*)&Kh[r][c8] =
                *(const uint4*)&g_khf[((size_t)(b*L_ + j0 + r))*D_ + h*DH_ + c8];
        }
        #pragma unroll
        for (int q = 0; q < 2; q++) {
            int idx = q*128 + tid;
            int r = idx & 31, c0 = (idx >> 5) * 8;
            uint4 vv = *(const uint4*)&g_vhf[((size_t)(b*L_ + j0 + r))*D_ + h*DH_ + c0];
            const __half* hp = reinterpret_cast<const __half*>(&vv);
            #pragma unroll
            for (int i = 0; i < 8; i++) Vt[c0 + i][r] = hp[i];
        }
        __syncthreads();

        float sacc[4][4] = {};
        #pragma unroll
        for (int ks = 0; ks < 4; ks++) {
            uint32_t a[4], bb[2][4];
            ldsm4(a, a_ldQ + ks*32);
            ldsm4(bb[0], b_ldK + ks*32);
            ldsm4(bb[1], b_ldK + 16*QST_*2 + ks*32);
            #pragma unroll
            for (int nt = 0; nt < 4; nt++) {
                uint32_t bf[2] = { bb[nt >> 1][(nt & 1)*2], bb[nt >> 1][(nt & 1)*2 + 1] };
                mma16n8k16h(sacc[nt], a, bf);
            }
        }
        float cm0 = -1e30f, cm1 = -1e30f;
        #pragma unroll
        for (int nt = 0; nt < 4; nt++) {
            sacc[nt][0] *= 0.125f; sacc[nt][1] *= 0.125f;
            sacc[nt][2] *= 0.125f; sacc[nt][3] *= 0.125f;
            cm0 = fmaxf(cm0, fmaxf(sacc[nt][0], sacc[nt][1]));
            cm1 = fmaxf(cm1, fmaxf(sacc[nt][2], sacc[nt][3]));
        }
        cm0 = fmaxf(cm0, __shfl_xor_sync(0xffffffffu, cm0, 1));
        cm0 = fmaxf(cm0, __shfl_xor_sync(0xffffffffu, cm0, 2));
        cm1 = fmaxf(cm1, __shfl_xor_sync(0xffffffffu, cm1, 1));
        cm1 = fmaxf(cm1, __shfl_xor_sync(0xffffffffu, cm1, 2));
        float mn0 = fmaxf(m0r, cm0), mn1 = fmaxf(m1r, cm1);
        float al0 = expf(m0r - mn0), al1 = expf(m1r - mn1);
        m0r = mn0; m1r = mn1;
        float s0 = 0.f, s1 = 0.f;
        #pragma unroll
        for (int nt = 0; nt < 4; nt++) {
            float p0 = expf(sacc[nt][0] - mn0);
            float p1 = expf(sacc[nt][1] - mn0);
            float p2 = expf(sacc[nt][2] - mn1);
            float p3 = expf(sacc[nt][3] - mn1);
            s0 += p0 + p1; s1 += p2 + p3;
            int c = nt*8 + t*2;
            *reinterpret_cast<__half2*>(&Ph[w][g][c])     = __floats2half2_rn(p0, p1);
            *reinterpret_cast<__half2*>(&Ph[w][g + 8][c]) = __floats2half2_rn(p2, p3);
        }
        s0 += __shfl_xor_sync(0xffffffffu, s0, 1);
        s0 += __shfl_xor_sync(0xffffffffu, s0, 2);
        s1 += __shfl_xor_sync(0xffffffffu, s1, 1);
        s1 += __shfl_xor_sync(0xffffffffu, s1, 2);
        l0r = l0r*al0 + s0; l1r = l1r*al1 + s1;
        #pragma unroll
        for (int nt = 0; nt < 8; nt++) {
            accO[nt][0] *= al0; accO[nt][1] *= al0;
            accO[nt][2] *= al1; accO[nt][3] *= al1;
        }
        __syncwarp();
        #pragma unroll
        for (int ks = 0; ks < 2; ks++) {
            uint32_t a[4];
            ldsm4(a, a_ldP + ks*32);
            uint32_t bb[4][4];
            #pragma unroll
            for (int np = 0; np < 4; np++)
                ldsm4(bb[np], b_ldV + np*(16*VST_*2) + ks*32);
            #pragma unroll
            for (int nt = 0; nt < 8; nt++) {
                uint32_t bf[2] = { bb[nt >> 1][(nt & 1)*2], bb[nt >> 1][(nt & 1)*2 + 1] };
                mma16n8k16h(accO[nt], a, bf);
            }
        }
        __syncthreads();
    }

    const size_t slot0 = (size_t)(bh*NSPL_ + sp)*320 + it*64 + w*16 + g;
    const size_t slot1 = slot0 + 8;
    if (t == 0) {
        g_pm[slot0] = m0r; g_pl[slot0] = l0r;
        g_pm[slot1] = m1r; g_pl[slot1] = l1r;
    }
    #pragma unroll
    for (int nt = 0; nt < 8; nt++) {
        int c = nt*8 + t*2;
        g_po[slot0*64 + c]     = accO[nt][0];
        g_po[slot0*64 + c + 1] = accO[nt][1];
        g_po[slot1*64 + c]     = accO[nt][2];
        g_po[slot1*64 + c + 1] = accO[nt][3];
    }
}

// combine split-KV partials -> g_ctxh (fp16, feeds Wo GEMM)
__global__ __launch_bounds__(256) void attn_combine() {
    const int it = blockIdx.x, bh = blockIdx.y;
    const int b = bh / H_, h = bh % H_;
    __shared__ float ws[64][NSPL_];
    __shared__ float linv[64];
    const int tid = threadIdx.x;
    if (tid < 64) {
        size_t base = (size_t)(bh*NSPL_)*320 + it*64 + tid;
        float mv[NSPL_]; float m = -1e30f;
        #pragma unroll
        for (int s = 0; s < NSPL_; s++) { mv[s] = g_pm[base + (size_t)s*320]; m = fmaxf(m, mv[s]); }
        float l = 0.f;
        #pragma unroll
        for (int s = 0; s < NSPL_; s++) {
            float wv = expf(mv[s] - m);
            ws[tid][s] = wv;
            l += g_pl[base + (size_t)s*320] * wv;
        }
        linv[tid] = 1.f / l;
    }
    __syncthreads();
    #pragma unroll
    for (int q = 0; q < 16; q++) {
        int idx = q*256 + tid;
        int r = idx >> 6, c = idx & 63;
        int i = it*64 + r;
        if (i < KS_) {
            size_t slot = (size_t)(bh*NSPL_)*320 + it*64 + r;
            float acc = 0.f;
            #pragma unroll
            for (int s = 0; s < NSPL_; s++)
                acc += g_po[(slot + (size_t)s*320)*64 + c] * ws[r][s];
            g_ctxh[((size_t)(b*KS_ + i))*D_ + h*DH_ + c] = __float2half_rn(acc * linv[r]);
        }
    }
}

// ---------------- merge paths (Wo split-K fin fused) + residual + LN2 ------
__global__ void merge_ln2_kernel(const float* __restrict__ x, const float* __restrict__ g2,
                                 const float* __restrict__ b2, const float* __restrict__ bo) {
    int tok = blockIdx.x;
    int b = tok >> 11;
    int t = threadIdx.x;
    int pos = g_selpos[tok];
    float sc = g_scores[tok];
    __shared__ float sh[32];
    float hv[3]; float s = 0.f, sq = 0.f;
    #pragma unroll
    for (int i = 0; i < 3; i++) {
        int d = t + 256*i;
        float mg;
        if (pos >= 0) {
            mg = bo[d];
            size_t base = (size_t)pos*D_ + d;
            #pragma unroll
            for (int z = 0; z < QZ_; z++) mg += g_fp2[(size_t)z*MSEL_*D_ + base];
        } else {
            mg = g_mixb[(size_t)tok*D_ + d] + sc * g_pooledWm[b*D_ + d];
        }
        float u = x[(size_t)tok*D_ + d] + mg;
        hv[i] = u;
        g_h[(size_t)tok*D_ + d] = u;
        s += u; sq += u*u;
    }
    s  = blockReduceSum(s,  sh);
    sq = blockReduceSum(sq, sh);
    float mean = s * (1.f/D_);
    float rstd = rsqrtf(sq*(1.f/D_) - mean*mean + 1e-5f);
    #pragma unroll
    for (int i = 0; i < 3; i++) {
        int d = t + 256*i;
        g_n2h[(size_t)tok*D_ + d] = __float2half_rn((hv[i] - mean) * rstd * g2[d] + b2[d]);
    }
}

// ---------------- host launch ----------------
extern "C" void kernel_launch(void* const* d_in, const int* in_sizes, int n_in,
                              void* d_out, int out_size) {
    (void)in_sizes; (void)n_in; (void)out_size;
    const float* x   = (const float*)d_in[0];
    const float* g1  = (const float*)d_in[1];
    const float* b1  = (const float*)d_in[2];
    const float* g2  = (const float*)d_in[3];
    const float* b2  = (const float*)d_in[4];
    const float* Wr  = (const float*)d_in[5];
    const float* br  = (const float*)d_in[6];
    const float* Wq  = (const float*)d_in[7];
    const float* bq  = (const float*)d_in[8];
    const float* Wk  = (const float*)d_in[9];
    const float* bk  = (const float*)d_in[10];
    const float* Wv  = (const float*)d_in[11];
    const float* bv  = (const float*)d_in[12];
    const float* Wo  = (const float*)d_in[13];
    const float* bo  = (const float*)d_in[14];
    const float* Wm  = (const float*)d_in[15];
    const float* bm  = (const float*)d_in[16];
    const float* W1  = (const float*)d_in[17];
    const float* bf1 = (const float*)d_in[18];
    const float* W2  = (const float*)d_in[19];
    const float* bf2 = (const float*)d_in[20];
    float* out = (float*)d_out;

    float *p_fp2;
    __half *p_nh, *p_qselh, *p_ctxh, *p_n2h, *p_th, *p_whuf;
    int* p_selidx;
    float* p_bkvm;
    cudaGetSymbolAddress((void**)&p_nh,     g_nh);
    cudaGetSymbolAddress((void**)&p_bkvm,   g_bkvm);
    cudaGetSymbolAddress((void**)&p_qselh,  g_qselh);
    cudaGetSymbolAddress((void**)&p_ctxh,   g_ctxh);
    cudaGetSymbolAddress((void**)&p_n2h,    g_n2h);
    cudaGetSymbolAddress((void**)&p_th,     g_th);
    cudaGetSymbolAddress((void**)&p_whuf,   g_whuf);
    cudaGetSymbolAddress((void**)&p_selidx, g_selidx);
    cudaGetSymbolAddress((void**)&p_fp2,    g_fp2);

    __half* rKVM = p_whuf;                         // [2304][768]
    __half* rWq  = p_whuf + 3*(size_t)WSZ_;
    __half* rWo  = p_whuf + 4*(size_t)WSZ_;
    __half* rW1  = p_whuf + 5*(size_t)WSZ_;
    __half* rW2  = rW1 + (size_t)W1SZ_;

    // weight-prep table
    TP7 tp;
    tp.in[0]=Wk; tp.out[0]=rKVM + 0*(size_t)WSZ_; tp.K[0]=D_; tp.N[0]=D_;
    tp.in[1]=Wv; tp.out[1]=rKVM + 1*(size_t)WSZ_; tp.K[1]=D_; tp.N[1]=D_;
    tp.in[2]=Wm; tp.out[2]=rKVM + 2*(size_t)WSZ_; tp.K[2]=D_; tp.N[2]=D_;
    tp.in[3]=Wq; tp.out[3]=rWq;                   tp.K[3]=D_; tp.N[3]=D_;
    tp.in[4]=Wo; tp.out[4]=rWo;                   tp.K[4]=D_; tp.N[4]=D_;
    tp.in[5]=W1; tp.out[5]=rW1;                   tp.K[5]=D_; tp.N[5]=F_;
    tp.in[6]=W2; tp.out[6]=rW2;                   tp.K[6]=F_; tp.N[6]=D_;
    int total = 0;
    for (int s = 0; s < 7; s++) {
        tp.cum[s] = total;
        total += (tp.K[s]/64) * (tp.N[s]/32);
    }
    tp.cum[7] = total;   // 3744 == TPB_

    // 1. fused prologue: transposes + bias concat + LN1/router (one launch)
    prologue_kernel<<<TPB_ + 9 + BL_, 256>>>(tp, bk, bv, bm, x, g1, b1, Wr, br);
    // 2. fused top-k + pooled_part
    topkpool_kernel<<<B_ + 16*B_, 1024>>>();
    // 3. fused: K|V|mix projection + Q gather split-K + pooledwm (one launch)
    kvmq_kernel<<<KVMB_ + 60*QZ_ + 6*B_, 128>>>(p_nh, p_selidx, rKVM, p_bkvm, rWq, p_fp2, Wm);
    qfin<<<(MSEL_*D_ + 255)/256, 256>>>(bq);
    // 4. flash attention (split-KV=8, 32-key chunks) + combine
    flash_attn<<<dim3(5, B_*H_, NSPL_), 128>>>();
    attn_combine<<<dim3(5, B_*H_), 256>>>();
    // 5. Wo projection (split-K=4): partials consumed directly by merge_ln2
    gemm_h<4,false><<<dim3(D_/128, (MSEL_+127)/128, QZ_), 128>>>(p_ctxh, nullptr, rWo, nullptr, p_fp2, nullptr, MSEL_, D_, D_);
    // 6. merge (Wo fin fused) + residual + LN2
    merge_ln2_kernel<<<BL_, 256>>>(x, g2, b2, bo);
    // 7. FFN: FFN1 GELU -> fp16; FFN2 split-K=2 -> partials -> fin(out)
    gemm_h<1,false><<<dim3(F_/128, BL_/128), 128>>>(p_n2h, nullptr, rW1, bf1, nullptr, p_th, BL_, F_, D_);
    gemm_h<4,false><<<dim3(D_/128, BL_/128, 2), 128>>>(p_th, nullptr, rW2, nullptr, p_fp2, nullptr, BL_, D_, F_);
    ffn2_fin<<<(BL_*D_/4)/256, 256>>>(bf2, out);
}